// round 13
// baseline (speedup 1.0000x reference)
#include <cuda_runtime.h>
#include <cuda_bf16.h>
#include <math.h>
#include <stdint.h>

// ---------------- problem constants ----------------
#define Bq      8
#define Lq      2048
#define Tq      (Bq*Lq)        // 16384 tokens
#define DMv     320
#define DIv     1280
#define NST     16
#define DCONVK  8
#define DTRANK  20
#define XDv     52             // DTRANK + 2*NST
#define NBLK    4
#define NCH     32             // scan chunks
#define CL      (Lq/NCH)       // 64 steps per chunk

typedef uint32_t u32;
typedef __nv_bfloat16 bf16;

// ---------------- static device scratch (no allocations) ----------------
__device__ __align__(256) float g_bufA [Tq*DMv];          // fp32 (head input)
__device__ __align__(256) float g_dbc  [Tq*XDv];
__device__ __align__(256) float g_hc   [(size_t)Bq*NCH*NST*DIv];
__device__ __align__(256) float g_h0   [(size_t)Bq*NCH*NST*DIv];
__device__ __align__(256) float g_sumd [Bq*NCH*DIv];
__device__ float g_startmax;

// activations
__device__ __align__(256) bf16   g_bufAbf [Tq*DMv];
__device__ __align__(256) int8_t g_u8     [Tq*DMv];          // lin out, int8 (tanh*127)
__device__ __align__(256) bf16   g_xzbf   [(size_t)Tq*2*DIv];// inproj out (x | silu(z))
__device__ __align__(256) bf16   g_xconvbf[(size_t)Tq*DIv];
__device__ __align__(256) bf16   g_dbcbf  [Tq*56];           // stride 56
__device__ __align__(256) bf16   g_deltabf[(size_t)Tq*DIv];
__device__ __align__(256) bf16   g_ybf    [(size_t)Tq*DIv];

// weights
__device__ __align__(256) bf16   g_wlin[NBLK*320*320];
__device__ __align__(256) int8_t g_win8[NBLK*2560*320];      // inproj int8
__device__ __align__(256) float  g_wins[NBLK*2560];          // inproj per-row scales
__device__ __align__(256) bf16   g_wxp [NBLK*52*1280];
__device__ __align__(256) bf16   g_wdt [NBLK*1280*24];       // stride 24 (K=20 padded)
__device__ __align__(256) bf16   g_wout[NBLK*320*1280];

// ---------------- helpers ----------------
__device__ __forceinline__ u32 sptr(const void* p){
    return (u32)__cvta_generic_to_shared(p);
}
__device__ __forceinline__ void cpa16(u32 dst, const void* src, int sz){
    asm volatile("cp.async.ca.shared.global [%0], [%1], 16, %2;"
                 :: "r"(dst), "l"(src), "r"(sz) : "memory");
}
__device__ __forceinline__ void cpa16f(u32 dst, const void* src){
    asm volatile("cp.async.ca.shared.global [%0], [%1], 16;"
                 :: "r"(dst), "l"(src) : "memory");
}
#define CP_COMMIT() asm volatile("cp.async.commit_group;" ::: "memory")
#define CP_WAIT1()  asm volatile("cp.async.wait_group 1;" ::: "memory")

__device__ __forceinline__ void mma16(float* c, const u32* a, const u32* b){
    asm volatile("mma.sync.aligned.m16n8k16.row.col.f32.bf16.bf16.f32 "
        "{%0,%1,%2,%3}, {%4,%5,%6,%7}, {%8,%9}, {%0,%1,%2,%3};"
        : "+f"(c[0]), "+f"(c[1]), "+f"(c[2]), "+f"(c[3])
        : "r"(a[0]), "r"(a[1]), "r"(a[2]), "r"(a[3]), "r"(b[0]), "r"(b[1]));
}
__device__ __forceinline__ void mma8s(int* c, const u32* a, const u32* b){
    asm volatile("mma.sync.aligned.m16n8k32.row.col.s32.s8.s8.s32 "
        "{%0,%1,%2,%3}, {%4,%5,%6,%7}, {%8,%9}, {%0,%1,%2,%3};"
        : "+r"(c[0]), "+r"(c[1]), "+r"(c[2]), "+r"(c[3])
        : "r"(a[0]), "r"(a[1]), "r"(a[2]), "r"(a[3]), "r"(b[0]), "r"(b[1]));
}
__device__ __forceinline__ void ldsm4(u32& r0, u32& r1, u32& r2, u32& r3, u32 addr){
    asm volatile("ldmatrix.sync.aligned.m8n8.x4.shared.b16 {%0,%1,%2,%3}, [%4];"
        : "=r"(r0), "=r"(r1), "=r"(r2), "=r"(r3) : "r"(addr));
}

// ---------------- merged weight conversion (bf16 weights) ----------------
#define NQ1 (NBLK*320*320/4)      // wlin quads
#define NQ3 (NBLK*52*1280/4)      // wxp
#define NQ5 (NBLK*320*1280/4)     // wout
#define NQA (NQ1+NQ3+NQ5)
#define NDT (NBLK*1280*24)        // wdt padded elems
__global__ void k_cvtall(const float* __restrict__ lw,
                         const float* __restrict__ xw, const float* __restrict__ dw,
                         const float* __restrict__ ow){
    int i = blockIdx.x * 256 + threadIdx.x;
    if (i < NQA) {
        const float* s; bf16* d; int q = i;
        if (q < NQ1)                { s = lw; d = g_wlin; }
        else if ((q -= NQ1) < NQ3)  { s = xw; d = g_wxp;  }
        else                        { q -= NQ3; s = ow; d = g_wout; }
        float4 v = *(const float4*)(s + q*4);
        d[q*4+0] = __float2bfloat16(v.x);
        d[q*4+1] = __float2bfloat16(v.y);
        d[q*4+2] = __float2bfloat16(v.z);
        d[q*4+3] = __float2bfloat16(v.w);
    } else if (i < NQA + NDT) {
        int idx = i - NQA;
        int r = idx / 24, c = idx % 24;
        g_wdt[idx] = (c < 20) ? __float2bfloat16(dw[r*20 + c]) : __float2bfloat16(0.f);
    }
}

// ---------------- inproj weight int8 quantization (per-row scale) ----------------
// rows = NBLK*2560, K = 320. One warp per row.
__global__ void k_qw8(const float* __restrict__ w){
    int row  = blockIdx.x * 8 + (threadIdx.x >> 5);
    int lane = threadIdx.x & 31;
    if (row >= NBLK*2560) return;
    const float* wr = w + (size_t)row * 320;
    float m = 0.f;
    #pragma unroll
    for (int j = 0; j < 10; j++) m = fmaxf(m, fabsf(wr[lane + j*32]));
    #pragma unroll
    for (int o = 16; o > 0; o >>= 1) m = fmaxf(m, __shfl_xor_sync(0xffffffff, m, o));
    float scale = fmaxf(m, 1e-12f) * (1.f/127.f);
    if (lane == 0) g_wins[row] = scale;
    float inv = 127.f / fmaxf(m, 1e-12f);
    int8_t* d = g_win8 + (size_t)row * 320;
    #pragma unroll
    for (int j = 0; j < 10; j++) {
        int c = lane + j*32;
        d[c] = (int8_t)__float2int_rn(wr[c] * inv);
    }
}

// ---------------- start_max reduction ----------------
__global__ void k_startmax(const float* __restrict__ x){
    __shared__ float red[256];
    float m = -1e30f;
    for (int i = threadIdx.x; i < Tq; i += 256) m = fmaxf(m, x[i*4 + 2]);
    red[threadIdx.x] = m; __syncthreads();
    for (int s = 128; s > 0; s >>= 1){
        if (threadIdx.x < s) red[threadIdx.x] = fmaxf(red[threadIdx.x], red[threadIdx.x + s]);
        __syncthreads();
    }
    if (threadIdx.x == 0) g_startmax = red[0];
}

// ---------------- embedding: normalize + fc (K=4) -> bf16 ----------------
__global__ void k_embed(const float* __restrict__ x, const float* __restrict__ fcw,
                        const float* __restrict__ fcb){
    int t = blockIdx.x, c = threadIdx.x;
    float x0 = x[t*4+0], x1 = x[t*4+1], x2 = x[t*4+2], x3 = x[t*4+3];
    float n0 = x0 * (1.0f/255.0f), n1 = x1 * (1.0f/255.0f), n2 = x2 / g_startmax, n3 = x3;
    const float* w = fcw + c*4;
    float v = fcb[c] + n0*w[0] + n1*w[1] + n2*w[2] + n3*w[3];
    g_bufAbf[(size_t)t*DMv + c] = __float2bfloat16(v);
}

// ---------------- epilogue activation ----------------
// ACT: 0 none, 1 tanh, 2 softplus, 3 elu, 4 silu-on-z-half (col >= DIv)
template<int ACT> __device__ __forceinline__ float actf(float v, int col){
    if (ACT == 1) {
        float e = __expf(2.f * v);
        return 1.f - __fdividef(2.f, e + 1.f);
    }
    if (ACT == 2) {
        return (v > 20.f) ? v : __logf(1.f + __expf(v));
    }
    if (ACT == 3) {
        return (v > 0.f) ? v : (__expf(v) - 1.f);
    }
    if (ACT == 4) {
        if (col >= DIv) return v * __fdividef(1.f, 1.f + __expf(-v));
        return v;
    }
    return v;
}

// ---------------- bf16 mma.sync GEMM (lin/xproj/dtproj/outproj) ----------------
#define SBK 40
#define BN  64

template<int ACT>
__global__ void __launch_bounds__(256, 3) k_bgemm(
    const bf16* __restrict__ A, int lda,
    const bf16* __restrict__ W, int ldw,
    const float* __restrict__ bias,
    float* __restrict__ Cf, int ldc,
    bf16* __restrict__ Cb, int ldcb,
    int8_t* __restrict__ C8, int ldc8,
    int M, int N, int K)
{
    __shared__ __align__(16) uint16_t As[3][128][SBK];
    __shared__ __align__(16) uint16_t Bs[3][BN][SBK];
    const u32 BUFA = 128*SBK*2, BUFB = BN*SBK*2;

    int tid  = threadIdx.x;
    int lane = tid & 31, w = tid >> 5;
    int wm = (w & 3) * 32;
    int wn = (w >> 2) * 32;
    int g = lane >> 2, ti = lane & 3;
    int bm0 = blockIdx.y * 128, bn0 = blockIdx.x * BN;

    int lr  = lane & 7;
    int lb1 = (lane >> 3) & 1;
    int lb2 = (lane >> 4) & 1;
    u32 aoff[2];
    #pragma unroll
    for (int mf = 0; mf < 2; mf++)
        aoff[mf] = sptr(&As[0][wm + mf*16 + lr + 8*lb1][8*lb2]);
    u32 boff[2];
    #pragma unroll
    for (int nf2 = 0; nf2 < 2; nf2++)
        boff[nf2] = sptr(&Bs[0][wn + nf2*16 + lr + 8*lb2][8*lb1]);

    float acc[2][4][4];
    #pragma unroll
    for (int i = 0; i < 2; i++)
        #pragma unroll
        for (int j = 0; j < 4; j++)
            #pragma unroll
            for (int r = 0; r < 4; r++) acc[i][j][r] = 0.f;

    int nit = (K + 31) / 32;

    int srow = tid >> 1, scc = (tid & 1) * 2;
    int brn  = tid >> 2, bcc = tid & 3;
    const bf16* arow = A + (size_t)(bm0 + srow) * lda;
    int gn = bn0 + brn;
    int bvalid = (gn < N);
    const bf16* brow = bvalid ? (W + (size_t)gn * ldw) : W;

    u32 adst0 = sptr(&As[0][srow][0]) + scc*16;
    u32 bdst0 = sptr(&Bs[0][brn][0]) + bcc*16;

    auto stage = [&](int it, int buf){
        int k0 = it * 32;
        int kb = (k0 < K) ? k0 : 0;
        int remB = (K - k0) * 2;
        u32 adst = adst0 + buf*BUFA;
        #pragma unroll
        for (int c = 0; c < 2; c++) {
            int sv = remB - (scc + c)*16; sv = sv < 0 ? 0 : (sv > 16 ? 16 : sv);
            cpa16(adst + c*16, arow + kb + (scc + c)*8, sv);
        }
        {
            int sv = remB - bcc*16; sv = sv < 0 ? 0 : (sv > 16 ? 16 : sv);
            cpa16(bdst0 + buf*BUFB, brow + kb + bcc*8, bvalid ? sv : 0);
        }
        CP_COMMIT();
    };

    stage(0, 0);
    stage(1, 1);

    for (int itb = 0; itb < nit; itb += 3) {
        #pragma unroll
        for (int u = 0; u < 3; u++) {
            int it = itb + u;
            if (it >= nit) break;
            CP_WAIT1();
            __syncthreads();
            if (it + 2 < nit) stage(it + 2, (u + 2) % 3);
            else CP_COMMIT();

            u32 bufA = u * BUFA, bufB = u * BUFB;
            #pragma unroll
            for (int ks = 0; ks < 2; ks++) {
                u32 kadd = ks * 32;
                u32 afr[2][4];
                #pragma unroll
                for (int mf = 0; mf < 2; mf++)
                    ldsm4(afr[mf][0], afr[mf][1], afr[mf][2], afr[mf][3],
                          aoff[mf] + bufA + kadd);
                u32 bfr[4][2];
                #pragma unroll
                for (int nf2 = 0; nf2 < 2; nf2++)
                    ldsm4(bfr[2*nf2][0], bfr[2*nf2][1], bfr[2*nf2+1][0], bfr[2*nf2+1][1],
                          boff[nf2] + bufB + kadd);
                #pragma unroll
                for (int mf = 0; mf < 2; mf++)
                    #pragma unroll
                    for (int nf = 0; nf < 4; nf++)
                        mma16(acc[mf][nf], afr[mf], bfr[nf]);
            }
        }
    }

    // ---- epilogue ----
    #pragma unroll
    for (int mf = 0; mf < 2; mf++) {
        int mrow0 = bm0 + wm + mf*16 + g;
        #pragma unroll
        for (int nf = 0; nf < 4; nf++) {
            int col = bn0 + wn + nf*8 + 2*ti;
            float b0 = 0.f, b1 = 0.f;
            if (bias) {
                if (col   < N) b0 = bias[col];
                if (col+1 < N) b1 = bias[col+1];
            }
            #pragma unroll
            for (int h = 0; h < 2; h++) {
                int m = mrow0 + h*8;
                float v0 = actf<ACT>(acc[mf][nf][2*h+0] + b0, col);
                float v1 = actf<ACT>(acc[mf][nf][2*h+1] + b1, col+1);
                if (Cf) {
                    float* crow = Cf + (size_t)m * ldc;
                    if (col + 1 < N)      *(float2*)(crow + col) = make_float2(v0, v1);
                    else if (col < N)     crow[col] = v0;
                }
                if (Cb) {
                    bf16* brow2 = Cb + (size_t)m * ldcb;
                    if (col + 1 < N)      *(__nv_bfloat162*)(brow2 + col) = __floats2bfloat162_rn(v0, v1);
                    else if (col < N)     brow2[col] = __float2bfloat16(v0);
                }
                if (C8) {
                    int8_t* srw = C8 + (size_t)m * ldc8;
                    if (col + 1 < N) {
                        int8_t q0 = (int8_t)__float2int_rn(v0 * 127.f);
                        int8_t q1 = (int8_t)__float2int_rn(v1 * 127.f);
                        srw[col] = q0; srw[col+1] = q1;
                    } else if (col < N) {
                        srw[col] = (int8_t)__float2int_rn(v0 * 127.f);
                    }
                }
            }
        }
    }
}

// ---------------- int8 IMMA GEMM for inproj ----------------
// xz = A8[M,320] @ W8[2560,320]^T, dequant via per-row scale, silu on z half, bf16 out.
// CTA 128x64, BK=64 (=K/5), 256 threads, warp tile 32x32, 3-stage cp.async.
#define SBK8 80          // bytes per smem row (64 data + 16 pad); banks 20r+c/4 conflict-free

__global__ void __launch_bounds__(256, 3) k_igemm(
    const int8_t* __restrict__ A,
    const int8_t* __restrict__ W,
    const float* __restrict__ wscale,
    bf16* __restrict__ Cb)
{
    const int K = 320, N = 2560;
    __shared__ __align__(16) int8_t As[3][128][SBK8];
    __shared__ __align__(16) int8_t Bs[3][BN][SBK8];
    __shared__ float sws[BN];
    const u32 BUFA = 128*SBK8, BUFB = BN*SBK8;

    int tid  = threadIdx.x;
    int lane = tid & 31, w = tid >> 5;
    int wm = (w & 3) * 32;
    int wn = (w >> 2) * 32;
    int g = lane >> 2, ti = lane & 3;
    int bm0 = blockIdx.y * 128, bn0 = blockIdx.x * BN;

    if (tid < BN) sws[tid] = wscale[bn0 + tid];

    int lr  = lane & 7;
    int lb1 = (lane >> 3) & 1;
    int lb2 = (lane >> 4) & 1;
    u32 aoff[2];
    #pragma unroll
    for (int mf = 0; mf < 2; mf++)
        aoff[mf] = sptr(&As[0][wm + mf*16 + lr + 8*lb1][16*lb2]);
    u32 boff[2];
    #pragma unroll
    for (int nf2 = 0; nf2 < 2; nf2++)
        boff[nf2] = sptr(&Bs[0][wn + nf2*16 + lr + 8*lb2][16*lb1]);

    int acc[2][4][4];
    #pragma unroll
    for (int i = 0; i < 2; i++)
        #pragma unroll
        for (int j = 0; j < 4; j++)
            #pragma unroll
            for (int r = 0; r < 4; r++) acc[i][j][r] = 0;

    const int nit = 5;                    // K = 5 * 64 exactly

    // staging: A 128 rows x 64B = 512 chunks (2/thread); B 64 rows x 64B = 256 (1/thread)
    int srow = tid >> 1, scc = (tid & 1) * 2;
    int brn  = tid >> 2, bcc = tid & 3;
    const int8_t* arow = A + (size_t)(bm0 + srow) * K;
    const int8_t* brow = W + (size_t)(bn0 + brn) * K;
    u32 adst0 = sptr(&As[0][srow][0]) + scc*16;
    u32 bdst0 = sptr(&Bs[0][brn][0]) + bcc*16;

    auto stage = [&](int it, int buf){
        int k0 = it * 64;
        u32 adst = adst0 + buf*BUFA;
        cpa16f(adst,      arow + k0 + scc*16);
        cpa16f(adst + 16, arow + k0 + scc*16 + 16);
        cpa16f(bdst0 + buf*BUFB, brow + k0 + bcc*16);
        CP_COMMIT();
    };

    stage(0, 0);
    stage(1, 1);

    for (int itb = 0; itb < nit; itb += 3) {
        #pragma unroll
        for (int u = 0; u < 3; u++) {
            int it = itb + u;
            if (it >= nit) break;
            CP_WAIT1();
            __syncthreads();
            if (it + 2 < nit) stage(it + 2, (u + 2) % 3);
            else CP_COMMIT();

            u32 bufA = u * BUFA, bufB = u * BUFB;
            #pragma unroll
            for (int ks = 0; ks < 2; ks++) {
                u32 kadd = ks * 32;       // 32 bytes per k32 step
                u32 afr[2][4];
                #pragma unroll
                for (int mf = 0; mf < 2; mf++)
                    ldsm4(afr[mf][0], afr[mf][1], afr[mf][2], afr[mf][3],
                          aoff[mf] + bufA + kadd);
                u32 bfr[4][2];
                #pragma unroll
                for (int nf2 = 0; nf2 < 2; nf2++)
                    ldsm4(bfr[2*nf2][0], bfr[2*nf2][1], bfr[2*nf2+1][0], bfr[2*nf2+1][1],
                          boff[nf2] + bufB + kadd);
                #pragma unroll
                for (int mf = 0; mf < 2; mf++)
                    #pragma unroll
                    for (int nf = 0; nf < 4; nf++)
                        mma8s(acc[mf][nf], afr[mf], bfr[nf]);
            }
        }
    }

    // ---- epilogue: dequant + silu(z half) + bf16 store ----
    #pragma unroll
    for (int mf = 0; mf < 2; mf++) {
        int mrow0 = bm0 + wm + mf*16 + g;
        #pragma unroll
        for (int nf = 0; nf < 4; nf++) {
            int colL = wn + nf*8 + 2*ti;
            int col  = bn0 + colL;
            float s0 = sws[colL]     * (1.f/127.f);
            float s1 = sws[colL + 1] * (1.f/127.f);
            bool zhalf = (col >= DIv);
            #pragma unroll
            for (int h = 0; h < 2; h++) {
                int m = mrow0 + h*8;
                float v0 = __int2float_rn(acc[mf][nf][2*h+0]) * s0;
                float v1 = __int2float_rn(acc[mf][nf][2*h+1]) * s1;
                if (zhalf) {
                    v0 = v0 * __fdividef(1.f, 1.f + __expf(-v0));
                    v1 = v1 * __fdividef(1.f, 1.f + __expf(-v1));
                }
                *(__nv_bfloat162*)(Cb + (size_t)m * (2*DIv) + col) =
                    __floats2bfloat162_rn(v0, v1);
            }
        }
    }
}

// ---------------- depthwise causal conv (k=8) + bias + silu ----------------
__global__ void k_conv(const float* __restrict__ cw, const float* __restrict__ cb){
    int ch = blockIdx.y * 256 + threadIdx.x;
    int t0 = blockIdx.x * 16;
    int l0 = t0 & (Lq - 1);
    int tb = t0 - l0;

    float w[8];
    #pragma unroll
    for (int j = 0; j < 8; j++) w[j] = cw[ch*8 + j];
    float bv = cb[ch];

    float v[23];
    #pragma unroll
    for (int j = 0; j < 23; j++) {
        int l = l0 - 7 + j;
        v[j] = (l >= 0) ? __bfloat162float(g_xzbf[(size_t)(tb + l) * (2*DIv) + ch]) : 0.f;
    }
    #pragma unroll
    for (int o = 0; o < 16; o++) {
        float s = bv;
        #pragma unroll
        for (int j = 0; j < 8; j++) s = fmaf(v[o + j], w[j], s);
        float sil = s * __fdividef(1.f, 1.f + __expf(-s));
        g_xconvbf[(size_t)(t0 + o) * DIv + ch] = __float2bfloat16(sil);
    }
}

// ---------------- chunked selective scan (3 passes) ----------------
#define SW 8
#define SCH 64

__global__ void __launch_bounds__(SCH) k_scanA(const float* __restrict__ Alog){
    int b   = blockIdx.y / NCH;
    int c   = blockIdx.y % NCH;
    int ch0 = blockIdx.x * SCH;
    int tid = threadIdx.x;
    int ch  = ch0 + tid;

    __shared__ __align__(16) uint16_t sDh[3][SW][SCH];
    __shared__ __align__(16) uint16_t sXh[3][SW][SCH];
    __shared__ __align__(16) float sB[3][SW][16];

    float a[NST];
    bool fast = true;
    #pragma unroll
    for (int n = 0; n < NST; n++) {
        a[n] = -expf(Alog[ch*NST + n]);
        fast = fast && (fabsf(a[n] + (float)(n+1)) < 1e-4f * (float)(n+1));
    }

    float h[NST];
    #pragma unroll
    for (int n = 0; n < NST; n++) h[n] = 0.f;
    float cum = 0.f;

    const size_t tc0 = (size_t)b * Lq + (size_t)c * CL;

    auto stage = [&](int wnd){
        int buf = wnd % 3;
        int t0 = wnd * SW;
        {
            int s = tid >> 3, cc = (tid & 7) * 8;
            cpa16(sptr(&sDh[buf][s][cc]), &g_deltabf[(tc0 + t0 + s)*DIv + cc + ch0], 16);
            cpa16(sptr(&sXh[buf][s][cc]), &g_xconvbf[(tc0 + t0 + s)*DIv + cc + ch0], 16);
        }
        if (tid < SW*4) {
            int s = tid >> 2, cc = (tid & 3) * 4;
            cpa16(sptr(&sB[buf][s][cc]),
                  &g_dbc[(tc0 + t0 + s)*XDv + DTRANK + cc], 16);
        }
        CP_COMMIT();
    };

    stage(0);
    stage(1);

    for (int wnd = 0; wnd < CL/SW; wnd++) {
        int buf = wnd % 3;
        CP_WAIT1();
        __syncthreads();
        if (wnd + 2 < CL/SW) stage(wnd + 2);
        else CP_COMMIT();

        #pragma unroll
        for (int s = 0; s < SW; s++) {
            float delta, xv;
            {
                __nv_bfloat16 db, xb;
                *(uint16_t*)&db = sDh[buf][s][tid];
                *(uint16_t*)&xb = sXh[buf][s][tid];
                delta = __bfloat162float(db);
                xv = __bfloat162float(xb);
            }
            const float4* bq = (const float4*)&sB[buf][s][0];
            float4 q0 = bq[0], q1 = bq[1], q2 = bq[2], q3 = bq[3];
            float Bv[NST] = {q0.x,q0.y,q0.z,q0.w, q1.x,q1.y,q1.z,q1.w,
                             q2.x,q2.y,q2.z,q2.w, q3.x,q3.y,q3.z,q3.w};
            float dx = delta * xv;
            cum += delta;
            if (fast) {
                float p  = __expf(-delta);
                float p2 = p*p, p4 = p2*p2, p8 = p4*p4;
                float p3 = p2*p, p5 = p4*p, p6 = p4*p2, p7 = p4*p3;
                float pw[NST] = {p, p2, p3, p4, p5, p6, p7, p8,
                                 p8*p, p8*p2, p8*p3, p8*p4, p8*p5, p8*p6, p8*p7, p8*p8};
                #pragma unroll
                for (int n = 0; n < NST; n++)
                    h[n] = fmaf(pw[n], h[n], dx * Bv[n]);
            } else {
                #pragma unroll
                for (int n = 0; n < NST; n++)
                    h[n] = fmaf(__expf(delta * a[n]), h[n], dx * Bv[n]);
            }
        }
    }

    size_t base = ((size_t)(b*NCH + c) * NST) * DIv + ch;
    #pragma unroll
    for (int n = 0; n < NST; n++)
        g_hc[base + (size_t)n * DIv] = h[n];
    g_sumd[(b*NCH + c)*DIv + ch] = cum;
}

__global__ void k_scanB(const float* __restrict__ Alog){
    int id = blockIdx.x * 256 + threadIdx.x;
    if (id >= Bq*NST*DIv) return;
    int ch = id % DIv;
    int r  = id / DIv;
    int n  = r % NST;
    int b  = r / NST;
    float an = -expf(Alog[ch*NST + n]);
    float h0 = 0.f;
    for (int c = 0; c < NCH; c++) {
        size_t idx = ((size_t)(b*NCH + c) * NST + n) * DIv + ch;
        g_h0[idx] = h0;
        h0 = g_hc[idx] + __expf(an * g_sumd[(b*NCH + c)*DIv + ch]) * h0;
    }
}

__global__ void __launch_bounds__(SCH) k_scanC(const float* __restrict__ Alog,
                                               const float* __restrict__ Dw){
    int b   = blockIdx.y / NCH;
    int c   = blockIdx.y % NCH;
    int ch0 = blockIdx.x * SCH;
    int tid = threadIdx.x;
    int ch  = ch0 + tid;

    __shared__ __align__(16) uint16_t sDh[3][SW][SCH];
    __shared__ __align__(16) uint16_t sXh[3][SW][SCH];
    __shared__ __align__(16) uint16_t sZh[3][SW][SCH];
    __shared__ __align__(16) float sBC[3][SW][32];

    float a[NST];
    bool fast = true;
    #pragma unroll
    for (int n = 0; n < NST; n++) {
        a[n] = -expf(Alog[ch*NST + n]);
        fast = fast && (fabsf(a[n] + (float)(n+1)) < 1e-4f * (float)(n+1));
    }
    float Dd = Dw[ch];

    float h[NST];
    {
        size_t base = ((size_t)(b*NCH + c) * NST) * DIv + ch;
        #pragma unroll
        for (int n = 0; n < NST; n++)
            h[n] = g_h0[base + (size_t)n * DIv];
    }

    const size_t tc0 = (size_t)b * Lq + (size_t)c * CL;

    auto stage = [&](int wnd){
        int buf = wnd % 3;
        int t0 = wnd * SW;
        {
            int s = tid >> 3, cc = (tid & 7) * 8;
            cpa16(sptr(&sDh[buf][s][cc]), &g_deltabf[(tc0 + t0 + s)*DIv + cc + ch0], 16);
            cpa16(sptr(&sXh[buf][s][cc]), &g_xconvbf[(tc0 + t0 + s)*DIv + cc + ch0], 16);
            cpa16(sptr(&sZh[buf][s][cc]),
                  &g_xzbf[(tc0 + t0 + s)*(2*DIv) + DIv + cc + ch0], 16);
        }
        {
            int s = tid >> 3, cc = (tid & 7) * 4;
            cpa16(sptr(&sBC[buf][s][cc]),
                  &g_dbc[(tc0 + t0 + s)*XDv + DTRANK + cc], 16);
        }
        CP_COMMIT();
    };

    stage(0);
    stage(1);

    for (int wnd = 0; wnd < CL/SW; wnd++) {
        int buf = wnd % 3;
        CP_WAIT1();
        __syncthreads();
        if (wnd + 2 < CL/SW) stage(wnd + 2);
        else CP_COMMIT();

        #pragma unroll
        for (int s = 0; s < SW; s++) {
            float delta, xv, zv;
            {
                __nv_bfloat16 db, xb, zb;
                *(uint16_t*)&db = sDh[buf][s][tid];
                *(uint16_t*)&xb = sXh[buf][s][tid];
                *(uint16_t*)&zb = sZh[buf][s][tid];
                delta = __bfloat162float(db);
                xv = __bfloat162float(xb);
                zv = __bfloat162float(zb);        // already silu(z)
            }
            const float4* bcq = (const float4*)&sBC[buf][s][0];
            float4 q0 = bcq[0], q1 = bcq[1], q2 = bcq[2], q3 = bcq[3];
            float4 q4 = bcq[4], q5 = bcq[5], q6 = bcq[6], q7 = bcq[7];
            float Bv[NST] = {q0.x,q0.y,q0.z,q0.w, q1.x,q1.y,q1.z,q1.w,
                             q2.x,q2.y,q2.z,q2.w, q3.x,q3.y,q3.z,q3.w};
            float Cv[NST] = {q4.x,q4.y,q4.z,q4.w, q5.x,q5.y,q5.z,q5.w,
                             q6.x,q6.y,q6.z,q6.w, q7.x,q7.y,q7.z,q7.w};

            float dx = delta * xv;
            float y0 = 0.f, y1 = 0.f;
            if (fast) {
                float p  = __expf(-delta);
                float p2 = p*p, p4 = p2*p2, p8 = p4*p4;
                float p3 = p2*p, p5 = p4*p, p6 = p4*p2, p7 = p4*p3;
                float pw[NST] = {p, p2, p3, p4, p5, p6, p7, p8,
                                 p8*p, p8*p2, p8*p3, p8*p4, p8*p5, p8*p6, p8*p7, p8*p8};
                #pragma unroll
                for (int n = 0; n < NST; n += 2) {
                    h[n]   = fmaf(pw[n],   h[n],   dx * Bv[n]);
                    h[n+1] = fmaf(pw[n+1], h[n+1], dx * Bv[n+1]);
                    y0 = fmaf(h[n],   Cv[n],   y0);
                    y1 = fmaf(h[n+1], Cv[n+1], y1);
                }
            } else {
                #pragma unroll
                for (int n = 0; n < NST; n += 2) {
                    float dA0 = __expf(delta * a[n]);
                    float dA1 = __expf(delta * a[n+1]);
                    h[n]   = fmaf(dA0, h[n],   dx * Bv[n]);
                    h[n+1] = fmaf(dA1, h[n+1], dx * Bv[n+1]);
                    y0 = fmaf(h[n],   Cv[n],   y0);
                    y1 = fmaf(h[n+1], Cv[n+1], y1);
                }
            }
            float yy = fmaf(xv, Dd, y0 + y1);
            g_ybf[(tc0 + wnd*SW + s)*DIv + ch] = __float2bfloat16(yy * zv);
        }
    }
}

// ---------------- head MLP (M=8): 320 -> 512 -> 512 -> 1 ----------------
__global__ void __launch_bounds__(512) k_head(
    const float* __restrict__ w1, const float* __restrict__ b1,
    const float* __restrict__ w2, const float* __restrict__ b2,
    const float* __restrict__ w3, const float* __restrict__ b3,
    float* __restrict__ out)
{
    __shared__ float sh [8][320];
    __shared__ float sh1[8][512];
    __shared__ float sh2[8][512];
    int tid = threadIdx.x;

    for (int idx = tid; idx < 8*320; idx += 512) {
        int bb = idx / 320, c = idx % 320;
        sh[bb][c] = g_bufA[((size_t)bb * Lq + Lq - 1) * DMv + c];
    }
    __syncthreads();

    {
        int n = tid;
        float acc[8];
        #pragma unroll
        for (int bb = 0; bb < 8; bb++) acc[bb] = 0.f;
        const float* wr = w1 + (size_t)n * 320;
        for (int k = 0; k < 320; k++) {
            float wv = wr[k];
            #pragma unroll
            for (int bb = 0; bb < 8; bb++) acc[bb] = fmaf(wv, sh[bb][k], acc[bb]);
        }
        #pragma unroll
        for (int bb = 0; bb < 8; bb++) sh1[bb][n] = fmaxf(acc[bb] + b1[n], 0.f);
    }
    __syncthreads();

    {
        int n = tid;
        float acc[8];
        #pragma unroll
        for (int bb = 0; bb < 8; bb++) acc[bb] = 0.f;
        const float* wr = w2 + (size_t)n * 512;
        for (int k = 0; k < 512; k++) {
            float wv = wr[k];
            #pragma unroll
            for (int bb = 0; bb < 8; bb++) acc[bb] = fmaf(wv, sh1[bb][k], acc[bb]);
        }
        #pragma unroll
        for (int bb = 0; bb < 8; bb++) sh2[bb][n] = fmaxf(acc[bb] + b2[n], 0.f);
    }
    __syncthreads();

    if (tid < 8) {
        float acc = 0.f;
        for (int k = 0; k < 512; k++) acc = fmaf(w3[k], sh2[tid][k], acc);
        acc += b3[0];
        float scale = g_startmax / (1.f + logf((float)Lq));
        out[tid] = fmaxf(acc * scale, 0.f);
    }
}

// ---------------- host launch ----------------
extern "C" void kernel_launch(void* const* d_in, const int* in_sizes, int n_in,
                              void* d_out, int out_size)
{
    const float* x            = (const float*)d_in[0];
    const float* fc_w         = (const float*)d_in[1];
    const float* fc_b         = (const float*)d_in[2];
    const float* blk_lin_w    = (const float*)d_in[3];
    const float* blk_lin_b    = (const float*)d_in[4];
    const float* blk_inproj_w = (const float*)d_in[5];
    const float* blk_conv_w   = (const float*)d_in[6];
    const float* blk_conv_b   = (const float*)d_in[7];
    const float* blk_xproj_w  = (const float*)d_in[8];
    const float* blk_dtproj_w = (const float*)d_in[9];
    const float* blk_dtproj_b = (const float*)d_in[10];
    const float* blk_A_log    = (const float*)d_in[11];
    const float* blk_D        = (const float*)d_in[12];
    const float* blk_outproj_w= (const float*)d_in[13];
    const float* s1_w1        = (const float*)d_in[14];
    const float* s1_b1        = (const float*)d_in[15];
    const float* s1_w2        = (const float*)d_in[16];
    const float* s1_b2        = (const float*)d_in[17];
    const float* s1_w3        = (const float*)d_in[18];
    const float* s1_b3        = (const float*)d_in[19];

    void* p;
    cudaGetSymbolAddress(&p, g_dbc);     float* dbc      = (float*)p;
    cudaGetSymbolAddress(&p, g_bufA);    float* bufA     = (float*)p;
    cudaGetSymbolAddress(&p, g_bufAbf);  bf16* bufAbf    = (bf16*)p;
    cudaGetSymbolAddress(&p, g_u8);      int8_t* u8      = (int8_t*)p;
    cudaGetSymbolAddress(&p, g_xzbf);    bf16* xzbf      = (bf16*)p;
    cudaGetSymbolAddress(&p, g_xconvbf); bf16* xconvbf   = (bf16*)p;
    cudaGetSymbolAddress(&p, g_dbcbf);   bf16* dbcbf     = (bf16*)p;
    cudaGetSymbolAddress(&p, g_deltabf); bf16* deltabf   = (bf16*)p;
    cudaGetSymbolAddress(&p, g_ybf);     bf16* ybf       = (bf16*)p;
    cudaGetSymbolAddress(&p, g_wlin);    bf16* wlin      = (bf16*)p;
    cudaGetSymbolAddress(&p, g_win8);    int8_t* win8    = (int8_t*)p;
    cudaGetSymbolAddress(&p, g_wins);    float* wins     = (float*)p;
    cudaGetSymbolAddress(&p, g_wxp);     bf16* wxp       = (bf16*)p;
    cudaGetSymbolAddress(&p, g_wdt);     bf16* wdt       = (bf16*)p;
    cudaGetSymbolAddress(&p, g_wout);    bf16* wout      = (bf16*)p;

    // weight conversions (once per launch)
    k_cvtall<<<(NQA + NDT + 255)/256, 256>>>(blk_lin_w, blk_xproj_w,
                                             blk_dtproj_w, blk_outproj_w);
    k_qw8<<<(NBLK*2560 + 7)/8, 256>>>(blk_inproj_w);
    k_startmax<<<1, 256>>>(x);
    k_embed<<<Tq, DMv>>>(x, fc_w, fc_b);

    for (int i = 0; i < NBLK; i++) {
        const float* Alog = blk_A_log + (size_t)i*DIv*NST;

        // lin: tanh(bufA @ lin_w^T + b) -> u8 (int8, scale 127)   [Tq,320] K=320
        k_bgemm<1><<<dim3(5, Tq/128), 256>>>(
            bufAbf, DMv, wlin + (size_t)i*DMv*DMv, DMv,
            blk_lin_b + (size_t)i*DMv,
            (float*)nullptr, 0, (bf16*)nullptr, 0, u8, DMv, Tq, DMv, DMv);

        // inproj (int8 IMMA): u8 @ win8^T * scales -> xz(bf16, silu z half)
        k_igemm<<<dim3(40, Tq/128), 256>>>(
            u8, win8 + (size_t)i*2*DIv*DMv, wins + (size_t)i*2*DIv, xzbf);

        // depthwise causal conv + silu -> xconv(bf16)
        k_conv<<<dim3(Tq/16, DIv/256), 256>>>(
            blk_conv_w + (size_t)i*DIv*DCONVK, blk_conv_b + (size_t)i*DIv);

        // xproj: xconv @ xproj_w^T -> dbc (f32) + dbcbf (bf16)   [Tq,52] K=1280
        k_bgemm<0><<<dim3(1, Tq/128), 256>>>(
            xconvbf, DIv, wxp + (size_t)i*XDv*DIv, DIv,
            (const float*)nullptr,
            dbc, XDv, dbcbf, 56, (int8_t*)nullptr, 0, Tq, XDv, DIv);

        // dtproj: softplus(dt @ dtproj_w^T + b) -> delta(bf16)   [Tq,1280] K=20
        k_bgemm<2><<<dim3(20, Tq/128), 256>>>(
            dbcbf, 56, wdt + (size_t)i*DIv*24, 24,
            blk_dtproj_b + (size_t)i*DIv,
            (float*)nullptr, 0, deltabf, DIv, (int8_t*)nullptr, 0, Tq, DIv, DTRANK);

        // chunked selective scan -> y(bf16)
        k_scanA<<<dim3(DIv/SCH, Bq*NCH), SCH>>>(Alog);
        k_scanB<<<(Bq*NST*DIv + 255)/256, 256>>>(Alog);
        k_scanC<<<dim3(DIv/SCH, Bq*NCH), SCH>>>(Alog, blk_D + (size_t)i*DIv);

        // outproj: elu(y @ outproj_w^T) -> bufA (f32 + bf16)   [Tq,320] K=1280
        k_bgemm<3><<<dim3(5, Tq/128), 256>>>(
            ybf, DIv, wout + (size_t)i*DMv*DIv, DIv,
            (const float*)nullptr,
            bufA, DMv, bufAbf, DMv, (int8_t*)nullptr, 0, Tq, DMv, DIv);
    }

    k_head<<<1, 512>>>(s1_w1, s1_b1, s1_w2, s1_b2, s1_w3, s1_b3, (float*)d_out);
}

// round 14
// speedup vs baseline: 1.0512x; 1.0512x over previous
#include <cuda_runtime.h>
#include <cuda_bf16.h>
#include <math.h>
#include <stdint.h>

// ---------------- problem constants ----------------
#define Bq      8
#define Lq      2048
#define Tq      (Bq*Lq)        // 16384 tokens
#define DMv     320
#define DIv     1280
#define NST     16
#define DCONVK  8
#define DTRANK  20
#define XDv     52             // DTRANK + 2*NST
#define NBLK    4
#define NCH     16             // scan chunks
#define CL      (Lq/NCH)       // 128 steps per chunk

typedef uint32_t u32;
typedef unsigned long long ull;
typedef __nv_bfloat16 bf16;

// ---------------- static device scratch (no allocations) ----------------
__device__ __align__(256) float g_bufA [Tq*DMv];          // fp32 (head input)
__device__ __align__(256) float g_dbc  [Tq*XDv];
__device__ __align__(256) float g_hc   [(size_t)Bq*NCH*NST*DIv];
__device__ __align__(256) float g_h0   [(size_t)Bq*NCH*NST*DIv];
__device__ __align__(256) float g_sumd [Bq*NCH*DIv];
__device__ float g_startmax;

// bf16 activations
__device__ __align__(256) bf16 g_bufAbf [Tq*DMv];
__device__ __align__(256) bf16 g_ubf    [Tq*DMv];
__device__ __align__(256) bf16 g_xzbf   [(size_t)Tq*2*DIv];  // inproj out (x | silu(z))
__device__ __align__(256) bf16 g_xconvbf[(size_t)Tq*DIv];
__device__ __align__(256) bf16 g_dbcbf  [Tq*56];             // stride 56
__device__ __align__(256) bf16 g_deltabf[(size_t)Tq*DIv];
__device__ __align__(256) bf16 g_ybf    [(size_t)Tq*DIv];

// bf16 weights (converted once per launch)
__device__ __align__(256) bf16 g_wlin[NBLK*320*320];
__device__ __align__(256) bf16 g_win [NBLK*2560*320];
__device__ __align__(256) bf16 g_wxp [NBLK*52*1280];
__device__ __align__(256) bf16 g_wdt [NBLK*1280*24];         // stride 24 (K=20 padded)
__device__ __align__(256) bf16 g_wout[NBLK*320*1280];

// ---------------- helpers ----------------
__device__ __forceinline__ u32 sptr(const void* p){
    return (u32)__cvta_generic_to_shared(p);
}
__device__ __forceinline__ void cpa16(u32 dst, const void* src, int sz){
    asm volatile("cp.async.ca.shared.global [%0], [%1], 16, %2;"
                 :: "r"(dst), "l"(src), "r"(sz) : "memory");
}
#define CP_COMMIT() asm volatile("cp.async.commit_group;" ::: "memory")
#define CP_WAIT1()  asm volatile("cp.async.wait_group 1;" ::: "memory")

__device__ __forceinline__ void mma16(float* c, const u32* a, const u32* b){
    asm volatile("mma.sync.aligned.m16n8k16.row.col.f32.bf16.bf16.f32 "
        "{%0,%1,%2,%3}, {%4,%5,%6,%7}, {%8,%9}, {%0,%1,%2,%3};"
        : "+f"(c[0]), "+f"(c[1]), "+f"(c[2]), "+f"(c[3])
        : "r"(a[0]), "r"(a[1]), "r"(a[2]), "r"(a[3]), "r"(b[0]), "r"(b[1]));
}
__device__ __forceinline__ void ldsm4(u32& r0, u32& r1, u32& r2, u32& r3, u32 addr){
    asm volatile("ldmatrix.sync.aligned.m8n8.x4.shared.b16 {%0,%1,%2,%3}, [%4];"
        : "=r"(r0), "=r"(r1), "=r"(r2), "=r"(r3) : "r"(addr));
}
// f32x2 packed math
__device__ __forceinline__ ull pk2(float x, float y){
    ull r; asm("mov.b64 %0, {%1, %2};" : "=l"(r) : "f"(x), "f"(y)); return r;
}
__device__ __forceinline__ void upk2(ull v, float& x, float& y){
    asm("mov.b64 {%0, %1}, %2;" : "=f"(x), "=f"(y) : "l"(v));
}
__device__ __forceinline__ ull ffma2(ull a, ull b, ull c){
    ull d; asm("fma.rn.f32x2 %0, %1, %2, %3;" : "=l"(d) : "l"(a), "l"(b), "l"(c)); return d;
}
__device__ __forceinline__ ull fmul2(ull a, ull b){
    ull d; asm("mul.rn.f32x2 %0, %1, %2;" : "=l"(d) : "l"(a), "l"(b)); return d;
}

// ---------------- merged weight conversion ----------------
#define NQ1 (NBLK*320*320/4)      // wlin quads
#define NQ2 (NBLK*2560*320/4)     // win
#define NQ3 (NBLK*52*1280/4)      // wxp
#define NQ5 (NBLK*320*1280/4)     // wout
#define NQA (NQ1+NQ2+NQ3+NQ5)
#define NDT (NBLK*1280*24)        // wdt padded elems
__global__ void k_cvtall(const float* __restrict__ lw, const float* __restrict__ iw,
                         const float* __restrict__ xw, const float* __restrict__ dw,
                         const float* __restrict__ ow){
    int i = blockIdx.x * 256 + threadIdx.x;
    if (i < NQA) {
        const float* s; bf16* d; int q = i;
        if (q < NQ1)                { s = lw; d = g_wlin; }
        else if ((q -= NQ1) < NQ2)  { s = iw; d = g_win;  }
        else if ((q -= NQ2) < NQ3)  { s = xw; d = g_wxp;  }
        else                        { q -= NQ3; s = ow; d = g_wout; }
        float4 v = *(const float4*)(s + q*4);
        d[q*4+0] = __float2bfloat16(v.x);
        d[q*4+1] = __float2bfloat16(v.y);
        d[q*4+2] = __float2bfloat16(v.z);
        d[q*4+3] = __float2bfloat16(v.w);
    } else if (i < NQA + NDT) {
        int idx = i - NQA;
        int r = idx / 24, c = idx % 24;
        g_wdt[idx] = (c < 20) ? __float2bfloat16(dw[r*20 + c]) : __float2bfloat16(0.f);
    }
}

// ---------------- start_max reduction ----------------
__global__ void k_startmax(const float* __restrict__ x){
    __shared__ float red[256];
    float m = -1e30f;
    for (int i = threadIdx.x; i < Tq; i += 256) m = fmaxf(m, x[i*4 + 2]);
    red[threadIdx.x] = m; __syncthreads();
    for (int s = 128; s > 0; s >>= 1){
        if (threadIdx.x < s) red[threadIdx.x] = fmaxf(red[threadIdx.x], red[threadIdx.x + s]);
        __syncthreads();
    }
    if (threadIdx.x == 0) g_startmax = red[0];
}

// ---------------- embedding: normalize + fc (K=4) -> bf16 ----------------
// grid 256, block 320: each block handles 64 tokens, token normals staged in smem.
__global__ void __launch_bounds__(320) k_embed(
    const float* __restrict__ x, const float* __restrict__ fcw,
    const float* __restrict__ fcb){
    __shared__ float sx[64][4];
    int tid = threadIdx.x;
    int t0  = blockIdx.x * 64;
    float sm = g_startmax;
    if (tid < 256) {
        int tt = tid >> 2, c = tid & 3;
        float v = x[(size_t)(t0 + tt)*4 + c];
        if (c == 0 || c == 1) v *= (1.0f/255.0f);
        else if (c == 2) v /= sm;
        sx[tt][c] = v;
    }
    __syncthreads();
    const float* w = fcw + tid*4;
    float w0 = w[0], w1 = w[1], w2 = w[2], w3 = w[3];
    float bb = fcb[tid];
    for (int tt = 0; tt < 64; tt++) {
        float v = bb + sx[tt][0]*w0 + sx[tt][1]*w1 + sx[tt][2]*w2 + sx[tt][3]*w3;
        g_bufAbf[(size_t)(t0 + tt)*DMv + tid] = __float2bfloat16(v);
    }
}

// ---------------- epilogue activation ----------------
// ACT: 0 none, 1 tanh, 2 softplus, 3 elu, 4 silu-on-z-half (col >= DIv)
template<int ACT> __device__ __forceinline__ float actf(float v, int col){
    if (ACT == 1) {
        float e = __expf(2.f * v);
        return 1.f - __fdividef(2.f, e + 1.f);
    }
    if (ACT == 2) {
        return (v > 20.f) ? v : __logf(1.f + __expf(v));
    }
    if (ACT == 3) {
        return (v > 0.f) ? v : (__expf(v) - 1.f);
    }
    if (ACT == 4) {
        if (col >= DIv) return v * __fdividef(1.f, 1.f + __expf(-v));
        return v;
    }
    return v;
}

// ---------------- bf16 mma.sync GEMM, ldmatrix + 3-stage cp.async ----------------
#define SBK 40
#define BN  64

template<int ACT>
__global__ void __launch_bounds__(256, 3) k_bgemm(
    const bf16* __restrict__ A, int lda,
    const bf16* __restrict__ W, int ldw,
    const float* __restrict__ bias,
    float* __restrict__ Cf, int ldc,
    bf16* __restrict__ Cb, int ldcb,
    int M, int N, int K)
{
    __shared__ __align__(16) uint16_t As[3][128][SBK];
    __shared__ __align__(16) uint16_t Bs[3][BN][SBK];
    const u32 BUFA = 128*SBK*2, BUFB = BN*SBK*2;

    int tid  = threadIdx.x;
    int lane = tid & 31, w = tid >> 5;
    int wm = (w & 3) * 32;
    int wn = (w >> 2) * 32;
    int g = lane >> 2, ti = lane & 3;
    int bm0 = blockIdx.y * 128, bn0 = blockIdx.x * BN;

    int lr  = lane & 7;
    int lb1 = (lane >> 3) & 1;
    int lb2 = (lane >> 4) & 1;
    u32 aoff[2];
    #pragma unroll
    for (int mf = 0; mf < 2; mf++)
        aoff[mf] = sptr(&As[0][wm + mf*16 + lr + 8*lb1][8*lb2]);
    u32 boff[2];
    #pragma unroll
    for (int nf2 = 0; nf2 < 2; nf2++)
        boff[nf2] = sptr(&Bs[0][wn + nf2*16 + lr + 8*lb2][8*lb1]);

    float acc[2][4][4];
    #pragma unroll
    for (int i = 0; i < 2; i++)
        #pragma unroll
        for (int j = 0; j < 4; j++)
            #pragma unroll
            for (int r = 0; r < 4; r++) acc[i][j][r] = 0.f;

    int nit = (K + 31) / 32;

    int srow = tid >> 1, scc = (tid & 1) * 2;
    int brn  = tid >> 2, bcc = tid & 3;
    const bf16* arow = A + (size_t)(bm0 + srow) * lda;
    int gn = bn0 + brn;
    int bvalid = (gn < N);
    const bf16* brow = bvalid ? (W + (size_t)gn * ldw) : W;

    u32 adst0 = sptr(&As[0][srow][0]) + scc*16;
    u32 bdst0 = sptr(&Bs[0][brn][0]) + bcc*16;

    auto stage = [&](int it, int buf){
        int k0 = it * 32;
        int kb = (k0 < K) ? k0 : 0;
        int remB = (K - k0) * 2;
        u32 adst = adst0 + buf*BUFA;
        #pragma unroll
        for (int c = 0; c < 2; c++) {
            int sv = remB - (scc + c)*16; sv = sv < 0 ? 0 : (sv > 16 ? 16 : sv);
            cpa16(adst + c*16, arow + kb + (scc + c)*8, sv);
        }
        {
            int sv = remB - bcc*16; sv = sv < 0 ? 0 : (sv > 16 ? 16 : sv);
            cpa16(bdst0 + buf*BUFB, brow + kb + bcc*8, bvalid ? sv : 0);
        }
        CP_COMMIT();
    };

    stage(0, 0);
    stage(1, 1);

    for (int itb = 0; itb < nit; itb += 3) {
        #pragma unroll
        for (int u = 0; u < 3; u++) {
            int it = itb + u;
            if (it >= nit) break;
            CP_WAIT1();
            __syncthreads();
            if (it + 2 < nit) stage(it + 2, (u + 2) % 3);
            else CP_COMMIT();

            u32 bufA = u * BUFA, bufB = u * BUFB;
            #pragma unroll
            for (int ks = 0; ks < 2; ks++) {
                u32 kadd = ks * 32;
                u32 afr[2][4];
                #pragma unroll
                for (int mf = 0; mf < 2; mf++)
                    ldsm4(afr[mf][0], afr[mf][1], afr[mf][2], afr[mf][3],
                          aoff[mf] + bufA + kadd);
                u32 bfr[4][2];
                #pragma unroll
                for (int nf2 = 0; nf2 < 2; nf2++)
                    ldsm4(bfr[2*nf2][0], bfr[2*nf2][1], bfr[2*nf2+1][0], bfr[2*nf2+1][1],
                          boff[nf2] + bufB + kadd);
                #pragma unroll
                for (int mf = 0; mf < 2; mf++)
                    #pragma unroll
                    for (int nf = 0; nf < 4; nf++)
                        mma16(acc[mf][nf], afr[mf], bfr[nf]);
            }
        }
    }

    // ---- epilogue: bias + act + dual store ----
    #pragma unroll
    for (int mf = 0; mf < 2; mf++) {
        int mrow0 = bm0 + wm + mf*16 + g;
        #pragma unroll
        for (int nf = 0; nf < 4; nf++) {
            int col = bn0 + wn + nf*8 + 2*ti;
            float b0 = 0.f, b1 = 0.f;
            if (bias) {
                if (col   < N) b0 = bias[col];
                if (col+1 < N) b1 = bias[col+1];
            }
            #pragma unroll
            for (int h = 0; h < 2; h++) {
                int m = mrow0 + h*8;
                float v0 = actf<ACT>(acc[mf][nf][2*h+0] + b0, col);
                float v1 = actf<ACT>(acc[mf][nf][2*h+1] + b1, col+1);
                if (Cf) {
                    float* crow = Cf + (size_t)m * ldc;
                    if (col + 1 < N)      *(float2*)(crow + col) = make_float2(v0, v1);
                    else if (col < N)     crow[col] = v0;
                }
                if (Cb) {
                    bf16* brow2 = Cb + (size_t)m * ldcb;
                    if (col + 1 < N)      *(__nv_bfloat162*)(brow2 + col) = __floats2bfloat162_rn(v0, v1);
                    else if (col < N)     brow2[col] = __float2bfloat16(v0);
                }
            }
        }
    }
}

// ---------------- depthwise causal conv (k=8) + bias + silu ----------------
__global__ void k_conv(const float* __restrict__ cw, const float* __restrict__ cb){
    int ch = blockIdx.y * 256 + threadIdx.x;
    int t0 = blockIdx.x * 16;
    int l0 = t0 & (Lq - 1);
    int tb = t0 - l0;

    float w[8];
    #pragma unroll
    for (int j = 0; j < 8; j++) w[j] = cw[ch*8 + j];
    float bv = cb[ch];

    float v[23];
    #pragma unroll
    for (int j = 0; j < 23; j++) {
        int l = l0 - 7 + j;
        v[j] = (l >= 0) ? __bfloat162float(g_xzbf[(size_t)(tb + l) * (2*DIv) + ch]) : 0.f;
    }
    #pragma unroll
    for (int o = 0; o < 16; o++) {
        float s = bv;
        #pragma unroll
        for (int j = 0; j < 8; j++) s = fmaf(v[o + j], w[j], s);
        float sil = s * __fdividef(1.f, 1.f + __expf(-s));
        g_xconvbf[(size_t)(t0 + o) * DIv + ch] = __float2bfloat16(sil);
    }
}

// ---------------- chunked selective scan (3 passes, f32x2 inner math) ----------------
#define SW 8
#define SCH 64

// build pw pairs: w2[j] = (p^(2j+1), p^(2j+2)), j=0..7
__device__ __forceinline__ void powpairs(float p, ull* w2){
    float p2 = p*p, p4 = p2*p2, p8 = p4*p4;
    ull q  = pk2(p2, p2);
    ull r8 = pk2(p8, p8);
    w2[0] = pk2(p, p2);
    w2[1] = fmul2(w2[0], q);
    w2[2] = fmul2(w2[1], q);
    w2[3] = fmul2(w2[2], q);
    w2[4] = fmul2(w2[0], r8);
    w2[5] = fmul2(w2[1], r8);
    w2[6] = fmul2(w2[2], r8);
    w2[7] = fmul2(w2[3], r8);
}

// ---- Pass A: grid (DIv/SCH, Bq*NCH), block SCH ----
__global__ void __launch_bounds__(SCH) k_scanA(const float* __restrict__ Alog){
    int b   = blockIdx.y / NCH;
    int c   = blockIdx.y % NCH;
    int ch0 = blockIdx.x * SCH;
    int tid = threadIdx.x;
    int ch  = ch0 + tid;

    __shared__ __align__(16) uint16_t sDh[3][SW][SCH];
    __shared__ __align__(16) uint16_t sXh[3][SW][SCH];
    __shared__ __align__(16) float sB[3][SW][16];

    float a[NST];
    bool fast = true;
    #pragma unroll
    for (int n = 0; n < NST; n++) {
        a[n] = -expf(Alog[ch*NST + n]);
        fast = fast && (fabsf(a[n] + (float)(n+1)) < 1e-4f * (float)(n+1));
    }

    ull h2[8];
    #pragma unroll
    for (int j = 0; j < 8; j++) h2[j] = 0ULL;
    float cum = 0.f;

    const size_t tc0 = (size_t)b * Lq + (size_t)c * CL;

    auto stage = [&](int wnd){
        int buf = wnd % 3;
        int t0 = wnd * SW;
        {
            int s = tid >> 3, cc = (tid & 7) * 8;
            cpa16(sptr(&sDh[buf][s][cc]), &g_deltabf[(tc0 + t0 + s)*DIv + cc + ch0], 16);
            cpa16(sptr(&sXh[buf][s][cc]), &g_xconvbf[(tc0 + t0 + s)*DIv + cc + ch0], 16);
        }
        if (tid < SW*4) {
            int s = tid >> 2, cc = (tid & 3) * 4;
            cpa16(sptr(&sB[buf][s][cc]),
                  &g_dbc[(tc0 + t0 + s)*XDv + DTRANK + cc], 16);
        }
        CP_COMMIT();
    };

    stage(0);
    stage(1);

    for (int wnd = 0; wnd < CL/SW; wnd++) {
        int buf = wnd % 3;
        CP_WAIT1();
        __syncthreads();
        if (wnd + 2 < CL/SW) stage(wnd + 2);
        else CP_COMMIT();

        #pragma unroll
        for (int s = 0; s < SW; s++) {
            float delta, xv;
            {
                __nv_bfloat16 db, xb;
                *(uint16_t*)&db = sDh[buf][s][tid];
                *(uint16_t*)&xb = sXh[buf][s][tid];
                delta = __bfloat162float(db);
                xv = __bfloat162float(xb);
            }
            float dx = delta * xv;
            cum += delta;
            ull dd = pk2(dx, dx);
            const ulonglong2* bq = (const ulonglong2*)&sB[buf][s][0];
            ulonglong2 b0 = bq[0], b1 = bq[1], b2 = bq[2], b3 = bq[3];
            ull Bp[8] = {b0.x, b0.y, b1.x, b1.y, b2.x, b2.y, b3.x, b3.y};

            if (fast) {
                ull w2[8];
                powpairs(__expf(-delta), w2);
                #pragma unroll
                for (int j = 0; j < 8; j++)
                    h2[j] = ffma2(w2[j], h2[j], fmul2(dd, Bp[j]));
            } else {
                #pragma unroll
                for (int j = 0; j < 8; j++) {
                    ull ex = pk2(__expf(delta * a[2*j]), __expf(delta * a[2*j+1]));
                    h2[j] = ffma2(ex, h2[j], fmul2(dd, Bp[j]));
                }
            }
        }
    }

    size_t base = ((size_t)(b*NCH + c) * NST) * DIv + ch;
    #pragma unroll
    for (int j = 0; j < 8; j++) {
        float h0, h1;
        upk2(h2[j], h0, h1);
        g_hc[base + (size_t)(2*j    ) * DIv] = h0;
        g_hc[base + (size_t)(2*j + 1) * DIv] = h1;
    }
    g_sumd[(b*NCH + c)*DIv + ch] = cum;
}

// ---- Pass B: chain over chunks ----
__global__ void k_scanB(const float* __restrict__ Alog){
    int id = blockIdx.x * 256 + threadIdx.x;
    if (id >= Bq*NST*DIv) return;
    int ch = id % DIv;
    int r  = id / DIv;
    int n  = r % NST;
    int b  = r / NST;
    float an = -expf(Alog[ch*NST + n]);
    float h0 = 0.f;
    for (int c = 0; c < NCH; c++) {
        size_t idx = ((size_t)(b*NCH + c) * NST + n) * DIv + ch;
        g_h0[idx] = h0;
        h0 = g_hc[idx] + __expf(an * g_sumd[(b*NCH + c)*DIv + ch]) * h0;
    }
}

// ---- Pass C: exact scan per chunk seeded with h0 ----
__global__ void __launch_bounds__(SCH) k_scanC(const float* __restrict__ Alog,
                                               const float* __restrict__ Dw){
    int b   = blockIdx.y / NCH;
    int c   = blockIdx.y % NCH;
    int ch0 = blockIdx.x * SCH;
    int tid = threadIdx.x;
    int ch  = ch0 + tid;

    __shared__ __align__(16) uint16_t sDh[3][SW][SCH];
    __shared__ __align__(16) uint16_t sXh[3][SW][SCH];
    __shared__ __align__(16) uint16_t sZh[3][SW][SCH];
    __shared__ __align__(16) float sBC[3][SW][32];

    float a[NST];
    bool fast = true;
    #pragma unroll
    for (int n = 0; n < NST; n++) {
        a[n] = -expf(Alog[ch*NST + n]);
        fast = fast && (fabsf(a[n] + (float)(n+1)) < 1e-4f * (float)(n+1));
    }
    float Dd = Dw[ch];

    ull h2[8];
    {
        size_t base = ((size_t)(b*NCH + c) * NST) * DIv + ch;
        #pragma unroll
        for (int j = 0; j < 8; j++)
            h2[j] = pk2(g_h0[base + (size_t)(2*j)*DIv],
                        g_h0[base + (size_t)(2*j+1)*DIv]);
    }

    const size_t tc0 = (size_t)b * Lq + (size_t)c * CL;

    auto stage = [&](int wnd){
        int buf = wnd % 3;
        int t0 = wnd * SW;
        {
            int s = tid >> 3, cc = (tid & 7) * 8;
            cpa16(sptr(&sDh[buf][s][cc]), &g_deltabf[(tc0 + t0 + s)*DIv + cc + ch0], 16);
            cpa16(sptr(&sXh[buf][s][cc]), &g_xconvbf[(tc0 + t0 + s)*DIv + cc + ch0], 16);
            cpa16(sptr(&sZh[buf][s][cc]),
                  &g_xzbf[(tc0 + t0 + s)*(2*DIv) + DIv + cc + ch0], 16);
        }
        {
            int s = tid >> 3, cc = (tid & 7) * 4;
            cpa16(sptr(&sBC[buf][s][cc]),
                  &g_dbc[(tc0 + t0 + s)*XDv + DTRANK + cc], 16);
        }
        CP_COMMIT();
    };

    stage(0);
    stage(1);

    for (int wnd = 0; wnd < CL/SW; wnd++) {
        int buf = wnd % 3;
        CP_WAIT1();
        __syncthreads();
        if (wnd + 2 < CL/SW) stage(wnd + 2);
        else CP_COMMIT();

        #pragma unroll
        for (int s = 0; s < SW; s++) {
            float delta, xv, zv;
            {
                __nv_bfloat16 db, xb, zb;
                *(uint16_t*)&db = sDh[buf][s][tid];
                *(uint16_t*)&xb = sXh[buf][s][tid];
                *(uint16_t*)&zb = sZh[buf][s][tid];
                delta = __bfloat162float(db);
                xv = __bfloat162float(xb);
                zv = __bfloat162float(zb);        // already silu(z)
            }
            float dx = delta * xv;
            ull dd = pk2(dx, dx);
            const ulonglong2* bcq = (const ulonglong2*)&sBC[buf][s][0];
            ulonglong2 q0 = bcq[0], q1 = bcq[1], q2 = bcq[2], q3 = bcq[3];
            ulonglong2 q4 = bcq[4], q5 = bcq[5], q6 = bcq[6], q7 = bcq[7];
            ull Bp[8] = {q0.x, q0.y, q1.x, q1.y, q2.x, q2.y, q3.x, q3.y};
            ull Cp[8] = {q4.x, q4.y, q5.x, q5.y, q6.x, q6.y, q7.x, q7.y};

            ull y2 = 0ULL;
            if (fast) {
                ull w2[8];
                powpairs(__expf(-delta), w2);
                #pragma unroll
                for (int j = 0; j < 8; j++) {
                    h2[j] = ffma2(w2[j], h2[j], fmul2(dd, Bp[j]));
                    y2 = ffma2(h2[j], Cp[j], y2);
                }
            } else {
                #pragma unroll
                for (int j = 0; j < 8; j++) {
                    ull ex = pk2(__expf(delta * a[2*j]), __expf(delta * a[2*j+1]));
                    h2[j] = ffma2(ex, h2[j], fmul2(dd, Bp[j]));
                    y2 = ffma2(h2[j], Cp[j], y2);
                }
            }
            float y0, y1;
            upk2(y2, y0, y1);
            float yy = fmaf(xv, Dd, y0 + y1);
            g_ybf[(tc0 + wnd*SW + s)*DIv + ch] = __float2bfloat16(yy * zv);
        }
    }
}

// ---------------- head MLP (M=8): 320 -> 512 -> 512 -> 1 ----------------
__global__ void __launch_bounds__(512) k_head(
    const float* __restrict__ w1, const float* __restrict__ b1,
    const float* __restrict__ w2, const float* __restrict__ b2,
    const float* __restrict__ w3, const float* __restrict__ b3,
    float* __restrict__ out)
{
    __shared__ float sh [8][320];
    __shared__ float sh1[8][512];
    __shared__ float sh2[8][512];
    int tid = threadIdx.x;

    for (int idx = tid; idx < 8*320; idx += 512) {
        int bb = idx / 320, c = idx % 320;
        sh[bb][c] = g_bufA[((size_t)bb * Lq + Lq - 1) * DMv + c];
    }
    __syncthreads();

    {
        int n = tid;
        float acc[8];
        #pragma unroll
        for (int bb = 0; bb < 8; bb++) acc[bb] = 0.f;
        const float* wr = w1 + (size_t)n * 320;
        for (int k = 0; k < 320; k++) {
            float wv = wr[k];
            #pragma unroll
            for (int bb = 0; bb < 8; bb++) acc[bb] = fmaf(wv, sh[bb][k], acc[bb]);
        }
        #pragma unroll
        for (int bb = 0; bb < 8; bb++) sh1[bb][n] = fmaxf(acc[bb] + b1[n], 0.f);
    }
    __syncthreads();

    {
        int n = tid;
        float acc[8];
        #pragma unroll
        for (int bb = 0; bb < 8; bb++) acc[bb] = 0.f;
        const float* wr = w2 + (size_t)n * 512;
        for (int k = 0; k < 512; k++) {
            float wv = wr[k];
            #pragma unroll
            for (int bb = 0; bb < 8; bb++) acc[bb] = fmaf(wv, sh1[bb][k], acc[bb]);
        }
        #pragma unroll
        for (int bb = 0; bb < 8; bb++) sh2[bb][n] = fmaxf(acc[bb] + b2[n], 0.f);
    }
    __syncthreads();

    if (tid < 8) {
        float acc = 0.f;
        for (int k = 0; k < 512; k++) acc = fmaf(w3[k], sh2[tid][k], acc);
        acc += b3[0];
        float scale = g_startmax / (1.f + logf((float)Lq));
        out[tid] = fmaxf(acc * scale, 0.f);
    }
}

// ---------------- host launch ----------------
extern "C" void kernel_launch(void* const* d_in, const int* in_sizes, int n_in,
                              void* d_out, int out_size)
{
    const float* x            = (const float*)d_in[0];
    const float* fc_w         = (const float*)d_in[1];
    const float* fc_b         = (const float*)d_in[2];
    const float* blk_lin_w    = (const float*)d_in[3];
    const float* blk_lin_b    = (const float*)d_in[4];
    const float* blk_inproj_w = (const float*)d_in[5];
    const float* blk_conv_w   = (const float*)d_in[6];
    const float* blk_conv_b   = (const float*)d_in[7];
    const float* blk_xproj_w  = (const float*)d_in[8];
    const float* blk_dtproj_w = (const float*)d_in[9];
    const float* blk_dtproj_b = (const float*)d_in[10];
    const float* blk_A_log    = (const float*)d_in[11];
    const float* blk_D        = (const float*)d_in[12];
    const float* blk_outproj_w= (const float*)d_in[13];
    const float* s1_w1        = (const float*)d_in[14];
    const float* s1_b1        = (const float*)d_in[15];
    const float* s1_w2        = (const float*)d_in[16];
    const float* s1_b2        = (const float*)d_in[17];
    const float* s1_w3        = (const float*)d_in[18];
    const float* s1_b3        = (const float*)d_in[19];

    void* p;
    cudaGetSymbolAddress(&p, g_dbc);     float* dbc     = (float*)p;
    cudaGetSymbolAddress(&p, g_bufA);    float* bufA    = (float*)p;
    cudaGetSymbolAddress(&p, g_bufAbf);  bf16* bufAbf   = (bf16*)p;
    cudaGetSymbolAddress(&p, g_ubf);     bf16* ubf      = (bf16*)p;
    cudaGetSymbolAddress(&p, g_xzbf);    bf16* xzbf     = (bf16*)p;
    cudaGetSymbolAddress(&p, g_xconvbf); bf16* xconvbf  = (bf16*)p;
    cudaGetSymbolAddress(&p, g_dbcbf);   bf16* dbcbf    = (bf16*)p;
    cudaGetSymbolAddress(&p, g_deltabf); bf16* deltabf  = (bf16*)p;
    cudaGetSymbolAddress(&p, g_ybf);     bf16* ybf      = (bf16*)p;
    cudaGetSymbolAddress(&p, g_wlin);    bf16* wlin     = (bf16*)p;
    cudaGetSymbolAddress(&p, g_win);     bf16* win      = (bf16*)p;
    cudaGetSymbolAddress(&p, g_wxp);     bf16* wxp      = (bf16*)p;
    cudaGetSymbolAddress(&p, g_wdt);     bf16* wdt      = (bf16*)p;
    cudaGetSymbolAddress(&p, g_wout);    bf16* wout     = (bf16*)p;

    // merged weight conversion (1 launch)
    k_cvtall<<<(NQA + NDT + 255)/256, 256>>>(blk_lin_w, blk_inproj_w, blk_xproj_w,
                                             blk_dtproj_w, blk_outproj_w);
    k_startmax<<<1, 256>>>(x);
    k_embed<<<Tq/64, 320>>>(x, fc_w, fc_b);

    for (int i = 0; i < NBLK; i++) {
        const float* Alog = blk_A_log + (size_t)i*DIv*NST;

        // lin: tanh(bufA @ lin_w^T + b) -> u(bf16)   [Tq,320] K=320
        k_bgemm<1><<<dim3(5, Tq/128), 256>>>(
            bufAbf, DMv, wlin + (size_t)i*DMv*DMv, DMv,
            blk_lin_b + (size_t)i*DMv,
            (float*)nullptr, 0, ubf, DMv, Tq, DMv, DMv);

        // inproj: u @ inproj_w^T -> xz(bf16, silu on z half)   [Tq,2560] K=320
        k_bgemm<4><<<dim3(40, Tq/128), 256>>>(
            ubf, DMv, win + (size_t)i*2*DIv*DMv, DMv,
            (const float*)nullptr,
            (float*)nullptr, 0, xzbf, 2*DIv, Tq, 2*DIv, DMv);

        // depthwise causal conv + silu -> xconv(bf16)
        k_conv<<<dim3(Tq/16, DIv/256), 256>>>(
            blk_conv_w + (size_t)i*DIv*DCONVK, blk_conv_b + (size_t)i*DIv);

        // xproj: xconv @ xproj_w^T -> dbc (f32) + dbcbf (bf16)   [Tq,52] K=1280
        k_bgemm<0><<<dim3(1, Tq/128), 256>>>(
            xconvbf, DIv, wxp + (size_t)i*XDv*DIv, DIv,
            (const float*)nullptr,
            dbc, XDv, dbcbf, 56, Tq, XDv, DIv);

        // dtproj: softplus(dt @ dtproj_w^T + b) -> delta(bf16)   [Tq,1280] K=20
        k_bgemm<2><<<dim3(20, Tq/128), 256>>>(
            dbcbf, 56, wdt + (size_t)i*DIv*24, 24,
            blk_dtproj_b + (size_t)i*DIv,
            (float*)nullptr, 0, deltabf, DIv, Tq, DIv, DTRANK);

        // chunked selective scan -> y(bf16)
        k_scanA<<<dim3(DIv/SCH, Bq*NCH), SCH>>>(Alog);
        k_scanB<<<(Bq*NST*DIv + 255)/256, 256>>>(Alog);
        k_scanC<<<dim3(DIv/SCH, Bq*NCH), SCH>>>(Alog, blk_D + (size_t)i*DIv);

        // outproj: elu(y @ outproj_w^T) -> bufA (f32 + bf16)   [Tq,320] K=1280
        k_bgemm<3><<<dim3(5, Tq/128), 256>>>(
            ybf, DIv, wout + (size_t)i*DMv*DIv, DIv,
            (const float*)nullptr,
            bufA, DMv, bufAbf, DMv, Tq, DMv, DIv);
    }

    k_head<<<1, 512>>>(s1_w1, s1_b1, s1_w2, s1_b2, s1_w3, s1_b3, (float*)d_out);
}

// round 15
// speedup vs baseline: 1.0612x; 1.0095x over previous
#include <cuda_runtime.h>
#include <cuda_bf16.h>
#include <math.h>
#include <stdint.h>

// ---------------- problem constants ----------------
#define Bq      8
#define Lq      2048
#define Tq      (Bq*Lq)        // 16384 tokens
#define DMv     320
#define DIv     1280
#define NST     16
#define DCONVK  8
#define DTRANK  20
#define XDv     52             // DTRANK + 2*NST
#define NBLK    4
#define NCH     16             // scan chunks
#define CL      (Lq/NCH)       // 128 steps per chunk
#define PGRID   444            // persistent GEMM grid (148 SMs x 3 CTAs)

typedef uint32_t u32;
typedef __nv_bfloat16 bf16;

// ---------------- static device scratch (no allocations) ----------------
__device__ __align__(256) float g_bufA [Tq*DMv];          // fp32 (head input)
__device__ __align__(256) float g_dbc  [Tq*XDv];
__device__ __align__(256) float g_hc   [(size_t)Bq*NCH*NST*DIv];
__device__ __align__(256) float g_h0   [(size_t)Bq*NCH*NST*DIv];
__device__ __align__(256) float g_sumd [Bq*NCH*DIv];
__device__ float g_startmax;

// bf16 activations
__device__ __align__(256) bf16 g_bufAbf [Tq*DMv];
__device__ __align__(256) bf16 g_ubf    [Tq*DMv];
__device__ __align__(256) bf16 g_xzbf   [(size_t)Tq*2*DIv];  // inproj out (x | silu(z))
__device__ __align__(256) bf16 g_xconvbf[(size_t)Tq*DIv];
__device__ __align__(256) bf16 g_dbcbf  [Tq*56];             // stride 56
__device__ __align__(256) bf16 g_deltabf[(size_t)Tq*DIv];
__device__ __align__(256) bf16 g_ybf    [(size_t)Tq*DIv];

// bf16 weights (converted once per launch)
__device__ __align__(256) bf16 g_wlin[NBLK*320*320];
__device__ __align__(256) bf16 g_win [NBLK*2560*320];
__device__ __align__(256) bf16 g_wxp [NBLK*52*1280];
__device__ __align__(256) bf16 g_wdt [NBLK*1280*24];         // stride 24 (K=20 padded)
__device__ __align__(256) bf16 g_wout[NBLK*320*1280];

// ---------------- helpers ----------------
__device__ __forceinline__ u32 sptr(const void* p){
    return (u32)__cvta_generic_to_shared(p);
}
__device__ __forceinline__ void cpa16(u32 dst, const void* src, int sz){
    asm volatile("cp.async.ca.shared.global [%0], [%1], 16, %2;"
                 :: "r"(dst), "l"(src), "r"(sz) : "memory");
}
#define CP_COMMIT() asm volatile("cp.async.commit_group;" ::: "memory")
#define CP_WAIT1()  asm volatile("cp.async.wait_group 1;" ::: "memory")

__device__ __forceinline__ void mma16(float* c, const u32* a, const u32* b){
    asm volatile("mma.sync.aligned.m16n8k16.row.col.f32.bf16.bf16.f32 "
        "{%0,%1,%2,%3}, {%4,%5,%6,%7}, {%8,%9}, {%0,%1,%2,%3};"
        : "+f"(c[0]), "+f"(c[1]), "+f"(c[2]), "+f"(c[3])
        : "r"(a[0]), "r"(a[1]), "r"(a[2]), "r"(a[3]), "r"(b[0]), "r"(b[1]));
}
__device__ __forceinline__ void ldsm4(u32& r0, u32& r1, u32& r2, u32& r3, u32 addr){
    asm volatile("ldmatrix.sync.aligned.m8n8.x4.shared.b16 {%0,%1,%2,%3}, [%4];"
        : "=r"(r0), "=r"(r1), "=r"(r2), "=r"(r3) : "r"(addr));
}

// ---------------- merged weight conversion ----------------
#define NQ1 (NBLK*320*320/4)      // wlin quads
#define NQ2 (NBLK*2560*320/4)     // win
#define NQ3 (NBLK*52*1280/4)      // wxp
#define NQ5 (NBLK*320*1280/4)     // wout
#define NQA (NQ1+NQ2+NQ3+NQ5)
#define NDT (NBLK*1280*24)        // wdt padded elems
__global__ void k_cvtall(const float* __restrict__ lw, const float* __restrict__ iw,
                         const float* __restrict__ xw, const float* __restrict__ dw,
                         const float* __restrict__ ow){
    int i = blockIdx.x * 256 + threadIdx.x;
    if (i < NQA) {
        const float* s; bf16* d; int q = i;
        if (q < NQ1)                { s = lw; d = g_wlin; }
        else if ((q -= NQ1) < NQ2)  { s = iw; d = g_win;  }
        else if ((q -= NQ2) < NQ3)  { s = xw; d = g_wxp;  }
        else                        { q -= NQ3; s = ow; d = g_wout; }
        float4 v = *(const float4*)(s + q*4);
        d[q*4+0] = __float2bfloat16(v.x);
        d[q*4+1] = __float2bfloat16(v.y);
        d[q*4+2] = __float2bfloat16(v.z);
        d[q*4+3] = __float2bfloat16(v.w);
    } else if (i < NQA + NDT) {
        int idx = i - NQA;
        int r = idx / 24, c = idx % 24;
        g_wdt[idx] = (c < 20) ? __float2bfloat16(dw[r*20 + c]) : __float2bfloat16(0.f);
    }
}

// ---------------- start_max reduction ----------------
__global__ void k_startmax(const float* __restrict__ x){
    __shared__ float red[256];
    float m = -1e30f;
    for (int i = threadIdx.x; i < Tq; i += 256) m = fmaxf(m, x[i*4 + 2]);
    red[threadIdx.x] = m; __syncthreads();
    for (int s = 128; s > 0; s >>= 1){
        if (threadIdx.x < s) red[threadIdx.x] = fmaxf(red[threadIdx.x], red[threadIdx.x + s]);
        __syncthreads();
    }
    if (threadIdx.x == 0) g_startmax = red[0];
}

// ---------------- embedding: normalize + fc (K=4) -> bf16 ----------------
// grid Tq/64, block 320: each block handles 64 tokens, token normals staged in smem.
__global__ void __launch_bounds__(320) k_embed(
    const float* __restrict__ x, const float* __restrict__ fcw,
    const float* __restrict__ fcb){
    __shared__ float sx[64][4];
    int tid = threadIdx.x;
    int t0  = blockIdx.x * 64;
    float sm = g_startmax;
    if (tid < 256) {
        int tt = tid >> 2, c = tid & 3;
        float v = x[(size_t)(t0 + tt)*4 + c];
        if (c == 0 || c == 1) v *= (1.0f/255.0f);
        else if (c == 2) v /= sm;
        sx[tt][c] = v;
    }
    __syncthreads();
    const float* w = fcw + tid*4;
    float w0 = w[0], w1 = w[1], w2 = w[2], w3 = w[3];
    float bb = fcb[tid];
    for (int tt = 0; tt < 64; tt++) {
        float v = bb + sx[tt][0]*w0 + sx[tt][1]*w1 + sx[tt][2]*w2 + sx[tt][3]*w3;
        g_bufAbf[(size_t)(t0 + tt)*DMv + tid] = __float2bfloat16(v);
    }
}

// ---------------- epilogue activation ----------------
// ACT: 0 none, 1 tanh, 2 softplus, 3 elu, 4 silu-on-z-half (col >= DIv)
template<int ACT> __device__ __forceinline__ float actf(float v, int col){
    if (ACT == 1) {
        float e = __expf(2.f * v);
        return 1.f - __fdividef(2.f, e + 1.f);
    }
    if (ACT == 2) {
        return (v > 20.f) ? v : __logf(1.f + __expf(v));
    }
    if (ACT == 3) {
        return (v > 0.f) ? v : (__expf(v) - 1.f);
    }
    if (ACT == 4) {
        if (col >= DIv) return v * __fdividef(1.f, 1.f + __expf(-v));
        return v;
    }
    return v;
}

// ---------------- bf16 mma.sync GEMM, persistent tiles ----------------
// Fixed grid PGRID; each CTA loops over 128xBN tiles. 3-stage cp.async per tile.
#define SBK 40
#define BN  64

template<int ACT>
__global__ void __launch_bounds__(256, 3) k_bgemm(
    const bf16* __restrict__ A, int lda,
    const bf16* __restrict__ W, int ldw,
    const float* __restrict__ bias,
    float* __restrict__ Cf, int ldc,
    bf16* __restrict__ Cb, int ldcb,
    int ntx, int M, int N, int K)
{
    __shared__ __align__(16) uint16_t As[3][128][SBK];
    __shared__ __align__(16) uint16_t Bs[3][BN][SBK];
    const u32 BUFA = 128*SBK*2, BUFB = BN*SBK*2;

    int tid  = threadIdx.x;
    int lane = tid & 31, w = tid >> 5;
    int wm = (w & 3) * 32;
    int wn = (w >> 2) * 32;
    int g = lane >> 2, ti = lane & 3;

    int lr  = lane & 7;
    int lb1 = (lane >> 3) & 1;
    int lb2 = (lane >> 4) & 1;
    u32 aoff[2];
    #pragma unroll
    for (int mf = 0; mf < 2; mf++)
        aoff[mf] = sptr(&As[0][wm + mf*16 + lr + 8*lb1][8*lb2]);
    u32 boff[2];
    #pragma unroll
    for (int nf2 = 0; nf2 < 2; nf2++)
        boff[nf2] = sptr(&Bs[0][wn + nf2*16 + lr + 8*lb2][8*lb1]);

    int srow = tid >> 1, scc = (tid & 1) * 2;
    int brn  = tid >> 2, bcc = tid & 3;
    u32 adst0 = sptr(&As[0][srow][0]) + scc*16;
    u32 bdst0 = sptr(&Bs[0][brn][0]) + bcc*16;

    int nit = (K + 31) / 32;
    int ntiles = ntx * (M >> 7);

    for (int t = blockIdx.x; t < ntiles; t += PGRID) {
        int bx = t % ntx, by = t / ntx;
        int bm0 = by * 128, bn0 = bx * BN;

        float acc[2][4][4];
        #pragma unroll
        for (int i = 0; i < 2; i++)
            #pragma unroll
            for (int j = 0; j < 4; j++)
                #pragma unroll
                for (int r = 0; r < 4; r++) acc[i][j][r] = 0.f;

        const bf16* arow = A + (size_t)(bm0 + srow) * lda;
        int gn = bn0 + brn;
        int bvalid = (gn < N);
        const bf16* brow = bvalid ? (W + (size_t)gn * ldw) : W;

        auto stage = [&](int it, int buf){
            int k0 = it * 32;
            int kb = (k0 < K) ? k0 : 0;
            int remB = (K - k0) * 2;
            u32 adst = adst0 + buf*BUFA;
            #pragma unroll
            for (int c = 0; c < 2; c++) {
                int sv = remB - (scc + c)*16; sv = sv < 0 ? 0 : (sv > 16 ? 16 : sv);
                cpa16(adst + c*16, arow + kb + (scc + c)*8, sv);
            }
            {
                int sv = remB - bcc*16; sv = sv < 0 ? 0 : (sv > 16 ? 16 : sv);
                cpa16(bdst0 + buf*BUFB, brow + kb + bcc*8, bvalid ? sv : 0);
            }
            CP_COMMIT();
        };

        stage(0, 0);
        stage(1, 1);

        for (int itb = 0; itb < nit; itb += 3) {
            #pragma unroll
            for (int u = 0; u < 3; u++) {           // buf == u (itb multiple of 3)
                int it = itb + u;
                if (it >= nit) break;
                CP_WAIT1();
                __syncthreads();
                if (it + 2 < nit) stage(it + 2, (u + 2) % 3);
                else CP_COMMIT();

                u32 bufA = u * BUFA, bufB = u * BUFB;
                #pragma unroll
                for (int ks = 0; ks < 2; ks++) {
                    u32 kadd = ks * 32;
                    u32 afr[2][4];
                    #pragma unroll
                    for (int mf = 0; mf < 2; mf++)
                        ldsm4(afr[mf][0], afr[mf][1], afr[mf][2], afr[mf][3],
                              aoff[mf] + bufA + kadd);
                    u32 bfr[4][2];
                    #pragma unroll
                    for (int nf2 = 0; nf2 < 2; nf2++)
                        ldsm4(bfr[2*nf2][0], bfr[2*nf2][1], bfr[2*nf2+1][0], bfr[2*nf2+1][1],
                              boff[nf2] + bufB + kadd);
                    #pragma unroll
                    for (int mf = 0; mf < 2; mf++)
                        #pragma unroll
                        for (int nf = 0; nf < 4; nf++)
                            mma16(acc[mf][nf], afr[mf], bfr[nf]);
                }
            }
        }

        // ---- epilogue: bias + act + dual store ----
        #pragma unroll
        for (int mf = 0; mf < 2; mf++) {
            int mrow0 = bm0 + wm + mf*16 + g;
            #pragma unroll
            for (int nf = 0; nf < 4; nf++) {
                int col = bn0 + wn + nf*8 + 2*ti;
                float b0 = 0.f, b1 = 0.f;
                if (bias) {
                    if (col   < N) b0 = bias[col];
                    if (col+1 < N) b1 = bias[col+1];
                }
                #pragma unroll
                for (int h = 0; h < 2; h++) {
                    int m = mrow0 + h*8;
                    float v0 = actf<ACT>(acc[mf][nf][2*h+0] + b0, col);
                    float v1 = actf<ACT>(acc[mf][nf][2*h+1] + b1, col+1);
                    if (Cf) {
                        float* crow = Cf + (size_t)m * ldc;
                        if (col + 1 < N)      *(float2*)(crow + col) = make_float2(v0, v1);
                        else if (col < N)     crow[col] = v0;
                    }
                    if (Cb) {
                        bf16* brow2 = Cb + (size_t)m * ldcb;
                        if (col + 1 < N)      *(__nv_bfloat162*)(brow2 + col) = __floats2bfloat162_rn(v0, v1);
                        else if (col < N)     brow2[col] = __float2bfloat16(v0);
                    }
                }
            }
        }
        __syncthreads();   // all warps done with smem buffers before next tile staging
    }
}

// ---------------- depthwise causal conv (k=8) + bias + silu ----------------
__global__ void k_conv(const float* __restrict__ cw, const float* __restrict__ cb){
    int ch = blockIdx.y * 256 + threadIdx.x;
    int t0 = blockIdx.x * 16;
    int l0 = t0 & (Lq - 1);
    int tb = t0 - l0;

    float w[8];
    #pragma unroll
    for (int j = 0; j < 8; j++) w[j] = cw[ch*8 + j];
    float bv = cb[ch];

    float v[23];
    #pragma unroll
    for (int j = 0; j < 23; j++) {
        int l = l0 - 7 + j;
        v[j] = (l >= 0) ? __bfloat162float(g_xzbf[(size_t)(tb + l) * (2*DIv) + ch]) : 0.f;
    }
    #pragma unroll
    for (int o = 0; o < 16; o++) {
        float s = bv;
        #pragma unroll
        for (int j = 0; j < 8; j++) s = fmaf(v[o + j], w[j], s);
        float sil = s * __fdividef(1.f, 1.f + __expf(-s));
        g_xconvbf[(size_t)(t0 + o) * DIv + ch] = __float2bfloat16(sil);
    }
}

// ---------------- chunked selective scan (3 passes, scalar math) ----------------
#define SW 8
#define SCH 64

// ---- Pass A ----
__global__ void __launch_bounds__(SCH) k_scanA(const float* __restrict__ Alog){
    int b   = blockIdx.y / NCH;
    int c   = blockIdx.y % NCH;
    int ch0 = blockIdx.x * SCH;
    int tid = threadIdx.x;
    int ch  = ch0 + tid;

    __shared__ __align__(16) uint16_t sDh[3][SW][SCH];
    __shared__ __align__(16) uint16_t sXh[3][SW][SCH];
    __shared__ __align__(16) float sB[3][SW][16];

    float a[NST];
    bool fast = true;
    #pragma unroll
    for (int n = 0; n < NST; n++) {
        a[n] = -expf(Alog[ch*NST + n]);
        fast = fast && (fabsf(a[n] + (float)(n+1)) < 1e-4f * (float)(n+1));
    }

    float h[NST];
    #pragma unroll
    for (int n = 0; n < NST; n++) h[n] = 0.f;
    float cum = 0.f;

    const size_t tc0 = (size_t)b * Lq + (size_t)c * CL;

    auto stage = [&](int wnd){
        int buf = wnd % 3;
        int t0 = wnd * SW;
        {
            int s = tid >> 3, cc = (tid & 7) * 8;
            cpa16(sptr(&sDh[buf][s][cc]), &g_deltabf[(tc0 + t0 + s)*DIv + cc + ch0], 16);
            cpa16(sptr(&sXh[buf][s][cc]), &g_xconvbf[(tc0 + t0 + s)*DIv + cc + ch0], 16);
        }
        if (tid < SW*4) {
            int s = tid >> 2, cc = (tid & 3) * 4;
            cpa16(sptr(&sB[buf][s][cc]),
                  &g_dbc[(tc0 + t0 + s)*XDv + DTRANK + cc], 16);
        }
        CP_COMMIT();
    };

    stage(0);
    stage(1);

    for (int wnd = 0; wnd < CL/SW; wnd++) {
        int buf = wnd % 3;
        CP_WAIT1();
        __syncthreads();
        if (wnd + 2 < CL/SW) stage(wnd + 2);
        else CP_COMMIT();

        #pragma unroll
        for (int s = 0; s < SW; s++) {
            float delta, xv;
            {
                __nv_bfloat16 db, xb;
                *(uint16_t*)&db = sDh[buf][s][tid];
                *(uint16_t*)&xb = sXh[buf][s][tid];
                delta = __bfloat162float(db);
                xv = __bfloat162float(xb);
            }
            const float4* bq = (const float4*)&sB[buf][s][0];
            float4 q0 = bq[0], q1 = bq[1], q2 = bq[2], q3 = bq[3];
            float Bv[NST] = {q0.x,q0.y,q0.z,q0.w, q1.x,q1.y,q1.z,q1.w,
                             q2.x,q2.y,q2.z,q2.w, q3.x,q3.y,q3.z,q3.w};
            float dx = delta * xv;
            cum += delta;
            if (fast) {
                float p  = __expf(-delta);
                float p2 = p*p, p4 = p2*p2, p8 = p4*p4;
                float p3 = p2*p, p5 = p4*p, p6 = p4*p2, p7 = p4*p3;
                float pw[NST] = {p, p2, p3, p4, p5, p6, p7, p8,
                                 p8*p, p8*p2, p8*p3, p8*p4, p8*p5, p8*p6, p8*p7, p8*p8};
                #pragma unroll
                for (int n = 0; n < NST; n++)
                    h[n] = fmaf(pw[n], h[n], dx * Bv[n]);
            } else {
                #pragma unroll
                for (int n = 0; n < NST; n++)
                    h[n] = fmaf(__expf(delta * a[n]), h[n], dx * Bv[n]);
            }
        }
    }

    size_t base = ((size_t)(b*NCH + c) * NST) * DIv + ch;
    #pragma unroll
    for (int n = 0; n < NST; n++)
        g_hc[base + (size_t)n * DIv] = h[n];
    g_sumd[(b*NCH + c)*DIv + ch] = cum;
}

// ---- Pass B: chain over chunks ----
__global__ void k_scanB(const float* __restrict__ Alog){
    int id = blockIdx.x * 256 + threadIdx.x;
    if (id >= Bq*NST*DIv) return;
    int ch = id % DIv;
    int r  = id / DIv;
    int n  = r % NST;
    int b  = r / NST;
    float an = -expf(Alog[ch*NST + n]);
    float h0 = 0.f;
    for (int c = 0; c < NCH; c++) {
        size_t idx = ((size_t)(b*NCH + c) * NST + n) * DIv + ch;
        g_h0[idx] = h0;
        h0 = g_hc[idx] + __expf(an * g_sumd[(b*NCH + c)*DIv + ch]) * h0;
    }
}

// ---- Pass C: exact scan per chunk seeded with h0 ----
__global__ void __launch_bounds__(SCH) k_scanC(const float* __restrict__ Alog,
                                               const float* __restrict__ Dw){
    int b   = blockIdx.y / NCH;
    int c   = blockIdx.y % NCH;
    int ch0 = blockIdx.x * SCH;
    int tid = threadIdx.x;
    int ch  = ch0 + tid;

    __shared__ __align__(16) uint16_t sDh[3][SW][SCH];
    __shared__ __align__(16) uint16_t sXh[3][SW][SCH];
    __shared__ __align__(16) uint16_t sZh[3][SW][SCH];
    __shared__ __align__(16) float sBC[3][SW][32];

    float a[NST];
    bool fast = true;
    #pragma unroll
    for (int n = 0; n < NST; n++) {
        a[n] = -expf(Alog[ch*NST + n]);
        fast = fast && (fabsf(a[n] + (float)(n+1)) < 1e-4f * (float)(n+1));
    }
    float Dd = Dw[ch];

    float h[NST];
    {
        size_t base = ((size_t)(b*NCH + c) * NST) * DIv + ch;
        #pragma unroll
        for (int n = 0; n < NST; n++)
            h[n] = g_h0[base + (size_t)n * DIv];
    }

    const size_t tc0 = (size_t)b * Lq + (size_t)c * CL;

    auto stage = [&](int wnd){
        int buf = wnd % 3;
        int t0 = wnd * SW;
        {
            int s = tid >> 3, cc = (tid & 7) * 8;
            cpa16(sptr(&sDh[buf][s][cc]), &g_deltabf[(tc0 + t0 + s)*DIv + cc + ch0], 16);
            cpa16(sptr(&sXh[buf][s][cc]), &g_xconvbf[(tc0 + t0 + s)*DIv + cc + ch0], 16);
            cpa16(sptr(&sZh[buf][s][cc]),
                  &g_xzbf[(tc0 + t0 + s)*(2*DIv) + DIv + cc + ch0], 16);
        }
        {
            int s = tid >> 3, cc = (tid & 7) * 4;
            cpa16(sptr(&sBC[buf][s][cc]),
                  &g_dbc[(tc0 + t0 + s)*XDv + DTRANK + cc], 16);
        }
        CP_COMMIT();
    };

    stage(0);
    stage(1);

    for (int wnd = 0; wnd < CL/SW; wnd++) {
        int buf = wnd % 3;
        CP_WAIT1();
        __syncthreads();
        if (wnd + 2 < CL/SW) stage(wnd + 2);
        else CP_COMMIT();

        #pragma unroll
        for (int s = 0; s < SW; s++) {
            float delta, xv, zv;
            {
                __nv_bfloat16 db, xb, zb;
                *(uint16_t*)&db = sDh[buf][s][tid];
                *(uint16_t*)&xb = sXh[buf][s][tid];
                *(uint16_t*)&zb = sZh[buf][s][tid];
                delta = __bfloat162float(db);
                xv = __bfloat162float(xb);
                zv = __bfloat162float(zb);        // already silu(z)
            }
            const float4* bcq = (const float4*)&sBC[buf][s][0];
            float4 q0 = bcq[0], q1 = bcq[1], q2 = bcq[2], q3 = bcq[3];
            float4 q4 = bcq[4], q5 = bcq[5], q6 = bcq[6], q7 = bcq[7];
            float Bv[NST] = {q0.x,q0.y,q0.z,q0.w, q1.x,q1.y,q1.z,q1.w,
                             q2.x,q2.y,q2.z,q2.w, q3.x,q3.y,q3.z,q3.w};
            float Cv[NST] = {q4.x,q4.y,q4.z,q4.w, q5.x,q5.y,q5.z,q5.w,
                             q6.x,q6.y,q6.z,q6.w, q7.x,q7.y,q7.z,q7.w};

            float dx = delta * xv;
            float y0 = 0.f, y1 = 0.f;
            if (fast) {
                float p  = __expf(-delta);
                float p2 = p*p, p4 = p2*p2, p8 = p4*p4;
                float p3 = p2*p, p5 = p4*p, p6 = p4*p2, p7 = p4*p3;
                float pw[NST] = {p, p2, p3, p4, p5, p6, p7, p8,
                                 p8*p, p8*p2, p8*p3, p8*p4, p8*p5, p8*p6, p8*p7, p8*p8};
                #pragma unroll
                for (int n = 0; n < NST; n += 2) {
                    h[n]   = fmaf(pw[n],   h[n],   dx * Bv[n]);
                    h[n+1] = fmaf(pw[n+1], h[n+1], dx * Bv[n+1]);
                    y0 = fmaf(h[n],   Cv[n],   y0);
                    y1 = fmaf(h[n+1], Cv[n+1], y1);
                }
            } else {
                #pragma unroll
                for (int n = 0; n < NST; n += 2) {
                    float dA0 = __expf(delta * a[n]);
                    float dA1 = __expf(delta * a[n+1]);
                    h[n]   = fmaf(dA0, h[n],   dx * Bv[n]);
                    h[n+1] = fmaf(dA1, h[n+1], dx * Bv[n+1]);
                    y0 = fmaf(h[n],   Cv[n],   y0);
                    y1 = fmaf(h[n+1], Cv[n+1], y1);
                }
            }
            float yy = fmaf(xv, Dd, y0 + y1);
            g_ybf[(tc0 + wnd*SW + s)*DIv + ch] = __float2bfloat16(yy * zv);
        }
    }
}

// ---------------- head MLP (M=8): 320 -> 512 -> 512 -> 1 ----------------
__global__ void __launch_bounds__(512) k_head(
    const float* __restrict__ w1, const float* __restrict__ b1,
    const float* __restrict__ w2, const float* __restrict__ b2,
    const float* __restrict__ w3, const float* __restrict__ b3,
    float* __restrict__ out)
{
    __shared__ float sh [8][320];
    __shared__ float sh1[8][512];
    __shared__ float sh2[8][512];
    int tid = threadIdx.x;

    for (int idx = tid; idx < 8*320; idx += 512) {
        int bb = idx / 320, c = idx % 320;
        sh[bb][c] = g_bufA[((size_t)bb * Lq + Lq - 1) * DMv + c];
    }
    __syncthreads();

    {
        int n = tid;
        float acc[8];
        #pragma unroll
        for (int bb = 0; bb < 8; bb++) acc[bb] = 0.f;
        const float* wr = w1 + (size_t)n * 320;
        for (int k = 0; k < 320; k++) {
            float wv = wr[k];
            #pragma unroll
            for (int bb = 0; bb < 8; bb++) acc[bb] = fmaf(wv, sh[bb][k], acc[bb]);
        }
        #pragma unroll
        for (int bb = 0; bb < 8; bb++) sh1[bb][n] = fmaxf(acc[bb] + b1[n], 0.f);
    }
    __syncthreads();

    {
        int n = tid;
        float acc[8];
        #pragma unroll
        for (int bb = 0; bb < 8; bb++) acc[bb] = 0.f;
        const float* wr = w2 + (size_t)n * 512;
        for (int k = 0; k < 512; k++) {
            float wv = wr[k];
            #pragma unroll
            for (int bb = 0; bb < 8; bb++) acc[bb] = fmaf(wv, sh1[bb][k], acc[bb]);
        }
        #pragma unroll
        for (int bb = 0; bb < 8; bb++) sh2[bb][n] = fmaxf(acc[bb] + b2[n], 0.f);
    }
    __syncthreads();

    if (tid < 8) {
        float acc = 0.f;
        for (int k = 0; k < 512; k++) acc = fmaf(w3[k], sh2[tid][k], acc);
        acc += b3[0];
        float scale = g_startmax / (1.f + logf((float)Lq));
        out[tid] = fmaxf(acc * scale, 0.f);
    }
}

// ---------------- host launch ----------------
extern "C" void kernel_launch(void* const* d_in, const int* in_sizes, int n_in,
                              void* d_out, int out_size)
{
    const float* x            = (const float*)d_in[0];
    const float* fc_w         = (const float*)d_in[1];
    const float* fc_b         = (const float*)d_in[2];
    const float* blk_lin_w    = (const float*)d_in[3];
    const float* blk_lin_b    = (const float*)d_in[4];
    const float* blk_inproj_w = (const float*)d_in[5];
    const float* blk_conv_w   = (const float*)d_in[6];
    const float* blk_conv_b   = (const float*)d_in[7];
    const float* blk_xproj_w  = (const float*)d_in[8];
    const float* blk_dtproj_w = (const float*)d_in[9];
    const float* blk_dtproj_b = (const float*)d_in[10];
    const float* blk_A_log    = (const float*)d_in[11];
    const float* blk_D        = (const float*)d_in[12];
    const float* blk_outproj_w= (const float*)d_in[13];
    const float* s1_w1        = (const float*)d_in[14];
    const float* s1_b1        = (const float*)d_in[15];
    const float* s1_w2        = (const float*)d_in[16];
    const float* s1_b2        = (const float*)d_in[17];
    const float* s1_w3        = (const float*)d_in[18];
    const float* s1_b3        = (const float*)d_in[19];

    void* p;
    cudaGetSymbolAddress(&p, g_dbc);     float* dbc     = (float*)p;
    cudaGetSymbolAddress(&p, g_bufA);    float* bufA    = (float*)p;
    cudaGetSymbolAddress(&p, g_bufAbf);  bf16* bufAbf   = (bf16*)p;
    cudaGetSymbolAddress(&p, g_ubf);     bf16* ubf      = (bf16*)p;
    cudaGetSymbolAddress(&p, g_xzbf);    bf16* xzbf     = (bf16*)p;
    cudaGetSymbolAddress(&p, g_xconvbf); bf16* xconvbf  = (bf16*)p;
    cudaGetSymbolAddress(&p, g_dbcbf);   bf16* dbcbf    = (bf16*)p;
    cudaGetSymbolAddress(&p, g_deltabf); bf16* deltabf  = (bf16*)p;
    cudaGetSymbolAddress(&p, g_ybf);     bf16* ybf      = (bf16*)p;
    cudaGetSymbolAddress(&p, g_wlin);    bf16* wlin     = (bf16*)p;
    cudaGetSymbolAddress(&p, g_win);     bf16* win      = (bf16*)p;
    cudaGetSymbolAddress(&p, g_wxp);     bf16* wxp      = (bf16*)p;
    cudaGetSymbolAddress(&p, g_wdt);     bf16* wdt      = (bf16*)p;
    cudaGetSymbolAddress(&p, g_wout);    bf16* wout     = (bf16*)p;

    // merged weight conversion (1 launch)
    k_cvtall<<<(NQA + NDT + 255)/256, 256>>>(blk_lin_w, blk_inproj_w, blk_xproj_w,
                                             blk_dtproj_w, blk_outproj_w);
    k_startmax<<<1, 256>>>(x);
    k_embed<<<Tq/64, 320>>>(x, fc_w, fc_b);

    for (int i = 0; i < NBLK; i++) {
        const float* Alog = blk_A_log + (size_t)i*DIv*NST;

        // lin: tanh(bufA @ lin_w^T + b) -> u(bf16)   [Tq,320] K=320
        k_bgemm<1><<<PGRID, 256>>>(
            bufAbf, DMv, wlin + (size_t)i*DMv*DMv, DMv,
            blk_lin_b + (size_t)i*DMv,
            (float*)nullptr, 0, ubf, DMv, 5, Tq, DMv, DMv);

        // inproj: u @ inproj_w^T -> xz(bf16, silu on z half)   [Tq,2560] K=320
        k_bgemm<4><<<PGRID, 256>>>(
            ubf, DMv, win + (size_t)i*2*DIv*DMv, DMv,
            (const float*)nullptr,
            (float*)nullptr, 0, xzbf, 2*DIv, 40, Tq, 2*DIv, DMv);

        // depthwise causal conv + silu -> xconv(bf16)
        k_conv<<<dim3(Tq/16, DIv/256), 256>>>(
            blk_conv_w + (size_t)i*DIv*DCONVK, blk_conv_b + (size_t)i*DIv);

        // xproj: xconv @ xproj_w^T -> dbc (f32) + dbcbf (bf16)   [Tq,52] K=1280
        k_bgemm<0><<<PGRID, 256>>>(
            xconvbf, DIv, wxp + (size_t)i*XDv*DIv, DIv,
            (const float*)nullptr,
            dbc, XDv, dbcbf, 56, 1, Tq, XDv, DIv);

        // dtproj: softplus(dt @ dtproj_w^T + b) -> delta(bf16)   [Tq,1280] K=20
        k_bgemm<2><<<PGRID, 256>>>(
            dbcbf, 56, wdt + (size_t)i*DIv*24, 24,
            blk_dtproj_b + (size_t)i*DIv,
            (float*)nullptr, 0, deltabf, DIv, 20, Tq, DIv, DTRANK);

        // chunked selective scan -> y(bf16)
        k_scanA<<<dim3(DIv/SCH, Bq*NCH), SCH>>>(Alog);
        k_scanB<<<(Bq*NST*DIv + 255)/256, 256>>>(Alog);
        k_scanC<<<dim3(DIv/SCH, Bq*NCH), SCH>>>(Alog, blk_D + (size_t)i*DIv);

        // outproj: elu(y @ outproj_w^T) -> bufA (f32 + bf16)   [Tq,320] K=1280
        k_bgemm<3><<<PGRID, 256>>>(
            ybf, DIv, wout + (size_t)i*DMv*DIv, DIv,
            (const float*)nullptr,
            bufA, DMv, bufAbf, DMv, 5, Tq, DMv, DIv);
    }

    k_head<<<1, 512>>>(s1_w1, s1_b1, s1_w2, s1_b2, s1_w3, s1_b3, (float*)d_out);
}

// round 16
// speedup vs baseline: 1.0813x; 1.0190x over previous
#include <cuda_runtime.h>
#include <cuda_bf16.h>
#include <math.h>
#include <stdint.h>

// ---------------- problem constants ----------------
#define Bq      8
#define Lq      2048
#define Tq      (Bq*Lq)        // 16384 tokens
#define DMv     320
#define DIv     1280
#define NST     16
#define DCONVK  8
#define DTRANK  20
#define XDv     52             // DTRANK + 2*NST
#define NBLK    4
#define NCH     16             // scan chunks
#define CL      (Lq/NCH)       // 128 steps per chunk
#define KS      4              // xproj K-splits

typedef uint32_t u32;
typedef __nv_bfloat16 bf16;

// ---------------- static device scratch (no allocations) ----------------
__device__ __align__(256) float g_bufA [Tq*DMv];          // fp32 (head input)
__device__ __align__(256) float g_dbc  [Tq*XDv];
__device__ __align__(256) float g_xsp  [(size_t)KS*Tq*XDv]; // xproj split-K partials
__device__ __align__(256) float g_hc   [(size_t)Bq*NCH*NST*DIv];
__device__ __align__(256) float g_h0   [(size_t)Bq*NCH*NST*DIv];
__device__ __align__(256) float g_sumd [Bq*NCH*DIv];
__device__ float g_startmax;

// bf16 activations
__device__ __align__(256) bf16 g_bufAbf [Tq*DMv];
__device__ __align__(256) bf16 g_ubf    [Tq*DMv];
__device__ __align__(256) bf16 g_xzbf   [(size_t)Tq*2*DIv];  // inproj out (x | silu(z))
__device__ __align__(256) bf16 g_xconvbf[(size_t)Tq*DIv];
__device__ __align__(256) bf16 g_dbcbf  [Tq*56];             // stride 56
__device__ __align__(256) bf16 g_deltabf[(size_t)Tq*DIv];
__device__ __align__(256) bf16 g_ybf    [(size_t)Tq*DIv];

// bf16 weights (converted once per launch)
__device__ __align__(256) bf16 g_wlin[NBLK*320*320];
__device__ __align__(256) bf16 g_win [NBLK*2560*320];
__device__ __align__(256) bf16 g_wxp [NBLK*52*1280];
__device__ __align__(256) bf16 g_wdt [NBLK*1280*24];         // stride 24 (K=20 padded)
__device__ __align__(256) bf16 g_wout[NBLK*320*1280];

// ---------------- helpers ----------------
__device__ __forceinline__ u32 sptr(const void* p){
    return (u32)__cvta_generic_to_shared(p);
}
__device__ __forceinline__ void cpa16(u32 dst, const void* src, int sz){
    asm volatile("cp.async.ca.shared.global [%0], [%1], 16, %2;"
                 :: "r"(dst), "l"(src), "r"(sz) : "memory");
}
#define CP_COMMIT() asm volatile("cp.async.commit_group;" ::: "memory")
#define CP_WAIT1()  asm volatile("cp.async.wait_group 1;" ::: "memory")

__device__ __forceinline__ void mma16(float* c, const u32* a, const u32* b){
    asm volatile("mma.sync.aligned.m16n8k16.row.col.f32.bf16.bf16.f32 "
        "{%0,%1,%2,%3}, {%4,%5,%6,%7}, {%8,%9}, {%0,%1,%2,%3};"
        : "+f"(c[0]), "+f"(c[1]), "+f"(c[2]), "+f"(c[3])
        : "r"(a[0]), "r"(a[1]), "r"(a[2]), "r"(a[3]), "r"(b[0]), "r"(b[1]));
}
__device__ __forceinline__ void ldsm4(u32& r0, u32& r1, u32& r2, u32& r3, u32 addr){
    asm volatile("ldmatrix.sync.aligned.m8n8.x4.shared.b16 {%0,%1,%2,%3}, [%4];"
        : "=r"(r0), "=r"(r1), "=r"(r2), "=r"(r3) : "r"(addr));
}

// ---------------- merged weight conversion ----------------
#define NQ1 (NBLK*320*320/4)      // wlin quads
#define NQ2 (NBLK*2560*320/4)     // win
#define NQ3 (NBLK*52*1280/4)      // wxp
#define NQ5 (NBLK*320*1280/4)     // wout
#define NQA (NQ1+NQ2+NQ3+NQ5)
#define NDT (NBLK*1280*24)        // wdt padded elems
__global__ void k_cvtall(const float* __restrict__ lw, const float* __restrict__ iw,
                         const float* __restrict__ xw, const float* __restrict__ dw,
                         const float* __restrict__ ow){
    int i = blockIdx.x * 256 + threadIdx.x;
    if (i < NQA) {
        const float* s; bf16* d; int q = i;
        if (q < NQ1)                { s = lw; d = g_wlin; }
        else if ((q -= NQ1) < NQ2)  { s = iw; d = g_win;  }
        else if ((q -= NQ2) < NQ3)  { s = xw; d = g_wxp;  }
        else                        { q -= NQ3; s = ow; d = g_wout; }
        float4 v = *(const float4*)(s + q*4);
        d[q*4+0] = __float2bfloat16(v.x);
        d[q*4+1] = __float2bfloat16(v.y);
        d[q*4+2] = __float2bfloat16(v.z);
        d[q*4+3] = __float2bfloat16(v.w);
    } else if (i < NQA + NDT) {
        int idx = i - NQA;
        int r = idx / 24, c = idx % 24;
        g_wdt[idx] = (c < 20) ? __float2bfloat16(dw[r*20 + c]) : __float2bfloat16(0.f);
    }
}

// ---------------- start_max reduction ----------------
__global__ void k_startmax(const float* __restrict__ x){
    __shared__ float red[256];
    float m = -1e30f;
    for (int i = threadIdx.x; i < Tq; i += 256) m = fmaxf(m, x[i*4 + 2]);
    red[threadIdx.x] = m; __syncthreads();
    for (int s = 128; s > 0; s >>= 1){
        if (threadIdx.x < s) red[threadIdx.x] = fmaxf(red[threadIdx.x], red[threadIdx.x + s]);
        __syncthreads();
    }
    if (threadIdx.x == 0) g_startmax = red[0];
}

// ---------------- embedding: normalize + fc (K=4) -> bf16 ----------------
__global__ void __launch_bounds__(320) k_embed(
    const float* __restrict__ x, const float* __restrict__ fcw,
    const float* __restrict__ fcb){
    __shared__ float sx[64][4];
    int tid = threadIdx.x;
    int t0  = blockIdx.x * 64;
    float sm = g_startmax;
    if (tid < 256) {
        int tt = tid >> 2, c = tid & 3;
        float v = x[(size_t)(t0 + tt)*4 + c];
        if (c == 0 || c == 1) v *= (1.0f/255.0f);
        else if (c == 2) v /= sm;
        sx[tt][c] = v;
    }
    __syncthreads();
    const float* w = fcw + tid*4;
    float w0 = w[0], w1 = w[1], w2 = w[2], w3 = w[3];
    float bb = fcb[tid];
    for (int tt = 0; tt < 64; tt++) {
        float v = bb + sx[tt][0]*w0 + sx[tt][1]*w1 + sx[tt][2]*w2 + sx[tt][3]*w3;
        g_bufAbf[(size_t)(t0 + tt)*DMv + tid] = __float2bfloat16(v);
    }
}

// ---------------- epilogue activation ----------------
// ACT: 0 none, 1 tanh, 2 softplus, 3 elu, 4 silu-on-z-half (col >= DIv)
template<int ACT> __device__ __forceinline__ float actf(float v, int col){
    if (ACT == 1) {
        float e = __expf(2.f * v);
        return 1.f - __fdividef(2.f, e + 1.f);
    }
    if (ACT == 2) {
        return (v > 20.f) ? v : __logf(1.f + __expf(v));
    }
    if (ACT == 3) {
        return (v > 0.f) ? v : (__expf(v) - 1.f);
    }
    if (ACT == 4) {
        if (col >= DIv) return v * __fdividef(1.f, 1.f + __expf(-v));
        return v;
    }
    return v;
}

// ---------------- bf16 mma.sync GEMM, ldmatrix + 3-stage cp.async ----------------
#define SBK 40
#define BN  64

template<int ACT>
__global__ void __launch_bounds__(256, 3) k_bgemm(
    const bf16* __restrict__ A, int lda,
    const bf16* __restrict__ W, int ldw,
    const float* __restrict__ bias,
    float* __restrict__ Cf, int ldc,
    bf16* __restrict__ Cb, int ldcb,
    int M, int N, int K)
{
    __shared__ __align__(16) uint16_t As[3][128][SBK];
    __shared__ __align__(16) uint16_t Bs[3][BN][SBK];
    const u32 BUFA = 128*SBK*2, BUFB = BN*SBK*2;

    int tid  = threadIdx.x;
    int lane = tid & 31, w = tid >> 5;
    int wm = (w & 3) * 32;
    int wn = (w >> 2) * 32;
    int g = lane >> 2, ti = lane & 3;
    int bm0 = blockIdx.y * 128, bn0 = blockIdx.x * BN;

    int lr  = lane & 7;
    int lb1 = (lane >> 3) & 1;
    int lb2 = (lane >> 4) & 1;
    u32 aoff[2];
    #pragma unroll
    for (int mf = 0; mf < 2; mf++)
        aoff[mf] = sptr(&As[0][wm + mf*16 + lr + 8*lb1][8*lb2]);
    u32 boff[2];
    #pragma unroll
    for (int nf2 = 0; nf2 < 2; nf2++)
        boff[nf2] = sptr(&Bs[0][wn + nf2*16 + lr + 8*lb2][8*lb1]);

    float acc[2][4][4];
    #pragma unroll
    for (int i = 0; i < 2; i++)
        #pragma unroll
        for (int j = 0; j < 4; j++)
            #pragma unroll
            for (int r = 0; r < 4; r++) acc[i][j][r] = 0.f;

    int nit = (K + 31) / 32;

    int srow = tid >> 1, scc = (tid & 1) * 2;
    int brn  = tid >> 2, bcc = tid & 3;
    const bf16* arow = A + (size_t)(bm0 + srow) * lda;
    int gn = bn0 + brn;
    int bvalid = (gn < N);
    const bf16* brow = bvalid ? (W + (size_t)gn * ldw) : W;

    u32 adst0 = sptr(&As[0][srow][0]) + scc*16;
    u32 bdst0 = sptr(&Bs[0][brn][0]) + bcc*16;

    auto stage = [&](int it, int buf){
        int k0 = it * 32;
        int kb = (k0 < K) ? k0 : 0;
        int remB = (K - k0) * 2;
        u32 adst = adst0 + buf*BUFA;
        #pragma unroll
        for (int c = 0; c < 2; c++) {
            int sv = remB - (scc + c)*16; sv = sv < 0 ? 0 : (sv > 16 ? 16 : sv);
            cpa16(adst + c*16, arow + kb + (scc + c)*8, sv);
        }
        {
            int sv = remB - bcc*16; sv = sv < 0 ? 0 : (sv > 16 ? 16 : sv);
            cpa16(bdst0 + buf*BUFB, brow + kb + bcc*8, bvalid ? sv : 0);
        }
        CP_COMMIT();
    };

    stage(0, 0);
    stage(1, 1);

    for (int itb = 0; itb < nit; itb += 3) {
        #pragma unroll
        for (int u = 0; u < 3; u++) {           // buf == u (itb multiple of 3)
            int it = itb + u;
            if (it >= nit) break;
            CP_WAIT1();
            __syncthreads();
            if (it + 2 < nit) stage(it + 2, (u + 2) % 3);
            else CP_COMMIT();

            u32 bufA = u * BUFA, bufB = u * BUFB;
            #pragma unroll
            for (int ks = 0; ks < 2; ks++) {
                u32 kadd = ks * 32;
                u32 afr[2][4];
                #pragma unroll
                for (int mf = 0; mf < 2; mf++)
                    ldsm4(afr[mf][0], afr[mf][1], afr[mf][2], afr[mf][3],
                          aoff[mf] + bufA + kadd);
                u32 bfr[4][2];
                #pragma unroll
                for (int nf2 = 0; nf2 < 2; nf2++)
                    ldsm4(bfr[2*nf2][0], bfr[2*nf2][1], bfr[2*nf2+1][0], bfr[2*nf2+1][1],
                          boff[nf2] + bufB + kadd);
                #pragma unroll
                for (int mf = 0; mf < 2; mf++)
                    #pragma unroll
                    for (int nf = 0; nf < 4; nf++)
                        mma16(acc[mf][nf], afr[mf], bfr[nf]);
            }
        }
    }

    // ---- epilogue: bias + act + dual store ----
    #pragma unroll
    for (int mf = 0; mf < 2; mf++) {
        int mrow0 = bm0 + wm + mf*16 + g;
        #pragma unroll
        for (int nf = 0; nf < 4; nf++) {
            int col = bn0 + wn + nf*8 + 2*ti;
            float b0 = 0.f, b1 = 0.f;
            if (bias) {
                if (col   < N) b0 = bias[col];
                if (col+1 < N) b1 = bias[col+1];
            }
            #pragma unroll
            for (int h = 0; h < 2; h++) {
                int m = mrow0 + h*8;
                float v0 = actf<ACT>(acc[mf][nf][2*h+0] + b0, col);
                float v1 = actf<ACT>(acc[mf][nf][2*h+1] + b1, col+1);
                if (Cf) {
                    float* crow = Cf + (size_t)m * ldc;
                    if (col + 1 < N)      *(float2*)(crow + col) = make_float2(v0, v1);
                    else if (col < N)     crow[col] = v0;
                }
                if (Cb) {
                    bf16* brow2 = Cb + (size_t)m * ldcb;
                    if (col + 1 < N)      *(__nv_bfloat162*)(brow2 + col) = __floats2bfloat162_rn(v0, v1);
                    else if (col < N)     brow2[col] = __float2bfloat16(v0);
                }
            }
        }
    }
}

// ---------------- xproj split-K GEMM: grid (KS, Tq/128) ----------------
// partial[s] = xconv[:, s*320:(s+1)*320] @ wxp[:, s*320:(s+1)*320]^T -> g_xsp slice (f32)
__global__ void __launch_bounds__(256, 3) k_xgemm(
    const bf16* __restrict__ A,      // xconvbf, lda = DIv
    const bf16* __restrict__ W)      // wxp block base, ldw = DIv
{
    const int N = XDv, KSUB = DIv / KS;   // 52, 320
    __shared__ __align__(16) uint16_t As[3][128][SBK];
    __shared__ __align__(16) uint16_t Bs[3][BN][SBK];
    const u32 BUFA = 128*SBK*2, BUFB = BN*SBK*2;

    int tid  = threadIdx.x;
    int lane = tid & 31, w = tid >> 5;
    int wm = (w & 3) * 32;
    int wn = (w >> 2) * 32;
    int g = lane >> 2, ti = lane & 3;
    int ksp = blockIdx.x;                 // 0..KS-1
    int bm0 = blockIdx.y * 128;
    int koff = ksp * KSUB;

    int lr  = lane & 7;
    int lb1 = (lane >> 3) & 1;
    int lb2 = (lane >> 4) & 1;
    u32 aoff[2];
    #pragma unroll
    for (int mf = 0; mf < 2; mf++)
        aoff[mf] = sptr(&As[0][wm + mf*16 + lr + 8*lb1][8*lb2]);
    u32 boff[2];
    #pragma unroll
    for (int nf2 = 0; nf2 < 2; nf2++)
        boff[nf2] = sptr(&Bs[0][wn + nf2*16 + lr + 8*lb2][8*lb1]);

    float acc[2][4][4];
    #pragma unroll
    for (int i = 0; i < 2; i++)
        #pragma unroll
        for (int j = 0; j < 4; j++)
            #pragma unroll
            for (int r = 0; r < 4; r++) acc[i][j][r] = 0.f;

    const int nit = KSUB / 32;            // 10

    int srow = tid >> 1, scc = (tid & 1) * 2;
    int brn  = tid >> 2, bcc = tid & 3;
    const bf16* arow = A + (size_t)(bm0 + srow) * DIv + koff;
    int bvalid = (brn < N);
    const bf16* brow = bvalid ? (W + (size_t)brn * DIv + koff) : (W + koff);

    u32 adst0 = sptr(&As[0][srow][0]) + scc*16;
    u32 bdst0 = sptr(&Bs[0][brn][0]) + bcc*16;

    auto stage = [&](int it, int buf){
        int k0 = it * 32;
        u32 adst = adst0 + buf*BUFA;
        cpa16(adst,      arow + k0 + scc*8,       16);
        cpa16(adst + 16, arow + k0 + scc*8 + 8,   16);
        cpa16(bdst0 + buf*BUFB, brow + k0 + bcc*8, bvalid ? 16 : 0);
        CP_COMMIT();
    };

    stage(0, 0);
    stage(1, 1);

    for (int itb = 0; itb < nit; itb += 3) {
        #pragma unroll
        for (int u = 0; u < 3; u++) {
            int it = itb + u;
            if (it >= nit) break;
            CP_WAIT1();
            __syncthreads();
            if (it + 2 < nit) stage(it + 2, (u + 2) % 3);
            else CP_COMMIT();

            u32 bufA = u * BUFA, bufB = u * BUFB;
            #pragma unroll
            for (int ks = 0; ks < 2; ks++) {
                u32 kadd = ks * 32;
                u32 afr[2][4];
                #pragma unroll
                for (int mf = 0; mf < 2; mf++)
                    ldsm4(afr[mf][0], afr[mf][1], afr[mf][2], afr[mf][3],
                          aoff[mf] + bufA + kadd);
                u32 bfr[4][2];
                #pragma unroll
                for (int nf2 = 0; nf2 < 2; nf2++)
                    ldsm4(bfr[2*nf2][0], bfr[2*nf2][1], bfr[2*nf2+1][0], bfr[2*nf2+1][1],
                          boff[nf2] + bufB + kadd);
                #pragma unroll
                for (int mf = 0; mf < 2; mf++)
                    #pragma unroll
                    for (int nf = 0; nf < 4; nf++)
                        mma16(acc[mf][nf], afr[mf], bfr[nf]);
            }
        }
    }

    // ---- epilogue: store f32 partial ----
    float* out = g_xsp + (size_t)ksp * Tq * XDv;
    #pragma unroll
    for (int mf = 0; mf < 2; mf++) {
        int mrow0 = bm0 + wm + mf*16 + g;
        #pragma unroll
        for (int nf = 0; nf < 4; nf++) {
            int col = wn + nf*8 + 2*ti;
            #pragma unroll
            for (int h = 0; h < 2; h++) {
                int m = mrow0 + h*8;
                float* crow = out + (size_t)m * XDv;
                if (col + 1 < N) *(float2*)(crow + col) =
                    make_float2(acc[mf][nf][2*h+0], acc[mf][nf][2*h+1]);
                else if (col < N) crow[col] = acc[mf][nf][2*h+0];
            }
        }
    }
}

// reduce KS partials -> dbc (f32) + dbcbf (bf16, stride 56)
__global__ void k_xred(){
    int id = blockIdx.x * 256 + threadIdx.x;
    if (id >= Tq * XDv) return;
    float s = g_xsp[id] + g_xsp[(size_t)Tq*XDv + id]
            + g_xsp[(size_t)2*Tq*XDv + id] + g_xsp[(size_t)3*Tq*XDv + id];
    g_dbc[id] = s;
    int t = id / XDv, c = id % XDv;
    g_dbcbf[t*56 + c] = __float2bfloat16(s);
}

// ---------------- depthwise causal conv (k=8) + bias + silu ----------------
__global__ void k_conv(const float* __restrict__ cw, const float* __restrict__ cb){
    int ch = blockIdx.y * 256 + threadIdx.x;
    int t0 = blockIdx.x * 16;
    int l0 = t0 & (Lq - 1);
    int tb = t0 - l0;

    float w[8];
    #pragma unroll
    for (int j = 0; j < 8; j++) w[j] = cw[ch*8 + j];
    float bv = cb[ch];

    float v[23];
    #pragma unroll
    for (int j = 0; j < 23; j++) {
        int l = l0 - 7 + j;
        v[j] = (l >= 0) ? __bfloat162float(g_xzbf[(size_t)(tb + l) * (2*DIv) + ch]) : 0.f;
    }
    #pragma unroll
    for (int o = 0; o < 16; o++) {
        float s = bv;
        #pragma unroll
        for (int j = 0; j < 8; j++) s = fmaf(v[o + j], w[j], s);
        float sil = s * __fdividef(1.f, 1.f + __expf(-s));
        g_xconvbf[(size_t)(t0 + o) * DIv + ch] = __float2bfloat16(sil);
    }
}

// ---------------- chunked selective scan (3 passes, scalar math) ----------------
#define SW 8
#define SCH 64

// ---- Pass A ----
__global__ void __launch_bounds__(SCH) k_scanA(const float* __restrict__ Alog){
    int b   = blockIdx.y / NCH;
    int c   = blockIdx.y % NCH;
    int ch0 = blockIdx.x * SCH;
    int tid = threadIdx.x;
    int ch  = ch0 + tid;

    __shared__ __align__(16) uint16_t sDh[3][SW][SCH];
    __shared__ __align__(16) uint16_t sXh[3][SW][SCH];
    __shared__ __align__(16) float sB[3][SW][16];

    float a[NST];
    bool fast = true;
    #pragma unroll
    for (int n = 0; n < NST; n++) {
        a[n] = -expf(Alog[ch*NST + n]);
        fast = fast && (fabsf(a[n] + (float)(n+1)) < 1e-4f * (float)(n+1));
    }

    float h[NST];
    #pragma unroll
    for (int n = 0; n < NST; n++) h[n] = 0.f;
    float cum = 0.f;

    const size_t tc0 = (size_t)b * Lq + (size_t)c * CL;

    auto stage = [&](int wnd){
        int buf = wnd % 3;
        int t0 = wnd * SW;
        {
            int s = tid >> 3, cc = (tid & 7) * 8;
            cpa16(sptr(&sDh[buf][s][cc]), &g_deltabf[(tc0 + t0 + s)*DIv + cc + ch0], 16);
            cpa16(sptr(&sXh[buf][s][cc]), &g_xconvbf[(tc0 + t0 + s)*DIv + cc + ch0], 16);
        }
        if (tid < SW*4) {
            int s = tid >> 2, cc = (tid & 3) * 4;
            cpa16(sptr(&sB[buf][s][cc]),
                  &g_dbc[(tc0 + t0 + s)*XDv + DTRANK + cc], 16);
        }
        CP_COMMIT();
    };

    stage(0);
    stage(1);

    for (int wnd = 0; wnd < CL/SW; wnd++) {
        int buf = wnd % 3;
        CP_WAIT1();
        __syncthreads();
        if (wnd + 2 < CL/SW) stage(wnd + 2);
        else CP_COMMIT();

        #pragma unroll
        for (int s = 0; s < SW; s++) {
            float delta, xv;
            {
                __nv_bfloat16 db, xb;
                *(uint16_t*)&db = sDh[buf][s][tid];
                *(uint16_t*)&xb = sXh[buf][s][tid];
                delta = __bfloat162float(db);
                xv = __bfloat162float(xb);
            }
            const float4* bq = (const float4*)&sB[buf][s][0];
            float4 q0 = bq[0], q1 = bq[1], q2 = bq[2], q3 = bq[3];
            float Bv[NST] = {q0.x,q0.y,q0.z,q0.w, q1.x,q1.y,q1.z,q1.w,
                             q2.x,q2.y,q2.z,q2.w, q3.x,q3.y,q3.z,q3.w};
            float dx = delta * xv;
            cum += delta;
            if (fast) {
                float p  = __expf(-delta);
                float p2 = p*p, p4 = p2*p2, p8 = p4*p4;
                float p3 = p2*p, p5 = p4*p, p6 = p4*p2, p7 = p4*p3;
                float pw[NST] = {p, p2, p3, p4, p5, p6, p7, p8,
                                 p8*p, p8*p2, p8*p3, p8*p4, p8*p5, p8*p6, p8*p7, p8*p8};
                #pragma unroll
                for (int n = 0; n < NST; n++)
                    h[n] = fmaf(pw[n], h[n], dx * Bv[n]);
            } else {
                #pragma unroll
                for (int n = 0; n < NST; n++)
                    h[n] = fmaf(__expf(delta * a[n]), h[n], dx * Bv[n]);
            }
        }
    }

    size_t base = ((size_t)(b*NCH + c) * NST) * DIv + ch;
    #pragma unroll
    for (int n = 0; n < NST; n++)
        g_hc[base + (size_t)n * DIv] = h[n];
    g_sumd[(b*NCH + c)*DIv + ch] = cum;
}

// ---- Pass B: chain over chunks ----
__global__ void k_scanB(const float* __restrict__ Alog){
    int id = blockIdx.x * 256 + threadIdx.x;
    if (id >= Bq*NST*DIv) return;
    int ch = id % DIv;
    int r  = id / DIv;
    int n  = r % NST;
    int b  = r / NST;
    float an = -expf(Alog[ch*NST + n]);
    float h0 = 0.f;
    for (int c = 0; c < NCH; c++) {
        size_t idx = ((size_t)(b*NCH + c) * NST + n) * DIv + ch;
        g_h0[idx] = h0;
        h0 = g_hc[idx] + __expf(an * g_sumd[(b*NCH + c)*DIv + ch]) * h0;
    }
}

// ---- Pass C: exact scan per chunk seeded with h0 ----
__global__ void __launch_bounds__(SCH) k_scanC(const float* __restrict__ Alog,
                                               const float* __restrict__ Dw){
    int b   = blockIdx.y / NCH;
    int c   = blockIdx.y % NCH;
    int ch0 = blockIdx.x * SCH;
    int tid = threadIdx.x;
    int ch  = ch0 + tid;

    __shared__ __align__(16) uint16_t sDh[3][SW][SCH];
    __shared__ __align__(16) uint16_t sXh[3][SW][SCH];
    __shared__ __align__(16) uint16_t sZh[3][SW][SCH];
    __shared__ __align__(16) float sBC[3][SW][32];

    float a[NST];
    bool fast = true;
    #pragma unroll
    for (int n = 0; n < NST; n++) {
        a[n] = -expf(Alog[ch*NST + n]);
        fast = fast && (fabsf(a[n] + (float)(n+1)) < 1e-4f * (float)(n+1));
    }
    float Dd = Dw[ch];

    float h[NST];
    {
        size_t base = ((size_t)(b*NCH + c) * NST) * DIv + ch;
        #pragma unroll
        for (int n = 0; n < NST; n++)
            h[n] = g_h0[base + (size_t)n * DIv];
    }

    const size_t tc0 = (size_t)b * Lq + (size_t)c * CL;

    auto stage = [&](int wnd){
        int buf = wnd % 3;
        int t0 = wnd * SW;
        {
            int s = tid >> 3, cc = (tid & 7) * 8;
            cpa16(sptr(&sDh[buf][s][cc]), &g_deltabf[(tc0 + t0 + s)*DIv + cc + ch0], 16);
            cpa16(sptr(&sXh[buf][s][cc]), &g_xconvbf[(tc0 + t0 + s)*DIv + cc + ch0], 16);
            cpa16(sptr(&sZh[buf][s][cc]),
                  &g_xzbf[(tc0 + t0 + s)*(2*DIv) + DIv + cc + ch0], 16);
        }
        {
            int s = tid >> 3, cc = (tid & 7) * 4;
            cpa16(sptr(&sBC[buf][s][cc]),
                  &g_dbc[(tc0 + t0 + s)*XDv + DTRANK + cc], 16);
        }
        CP_COMMIT();
    };

    stage(0);
    stage(1);

    for (int wnd = 0; wnd < CL/SW; wnd++) {
        int buf = wnd % 3;
        CP_WAIT1();
        __syncthreads();
        if (wnd + 2 < CL/SW) stage(wnd + 2);
        else CP_COMMIT();

        #pragma unroll
        for (int s = 0; s < SW; s++) {
            float delta, xv, zv;
            {
                __nv_bfloat16 db, xb, zb;
                *(uint16_t*)&db = sDh[buf][s][tid];
                *(uint16_t*)&xb = sXh[buf][s][tid];
                *(uint16_t*)&zb = sZh[buf][s][tid];
                delta = __bfloat162float(db);
                xv = __bfloat162float(xb);
                zv = __bfloat162float(zb);        // already silu(z)
            }
            const float4* bcq = (const float4*)&sBC[buf][s][0];
            float4 q0 = bcq[0], q1 = bcq[1], q2 = bcq[2], q3 = bcq[3];
            float4 q4 = bcq[4], q5 = bcq[5], q6 = bcq[6], q7 = bcq[7];
            float Bv[NST] = {q0.x,q0.y,q0.z,q0.w, q1.x,q1.y,q1.z,q1.w,
                             q2.x,q2.y,q2.z,q2.w, q3.x,q3.y,q3.z,q3.w};
            float Cv[NST] = {q4.x,q4.y,q4.z,q4.w, q5.x,q5.y,q5.z,q5.w,
                             q6.x,q6.y,q6.z,q6.w, q7.x,q7.y,q7.z,q7.w};

            float dx = delta * xv;
            float y0 = 0.f, y1 = 0.f;
            if (fast) {
                float p  = __expf(-delta);
                float p2 = p*p, p4 = p2*p2, p8 = p4*p4;
                float p3 = p2*p, p5 = p4*p, p6 = p4*p2, p7 = p4*p3;
                float pw[NST] = {p, p2, p3, p4, p5, p6, p7, p8,
                                 p8*p, p8*p2, p8*p3, p8*p4, p8*p5, p8*p6, p8*p7, p8*p8};
                #pragma unroll
                for (int n = 0; n < NST; n += 2) {
                    h[n]   = fmaf(pw[n],   h[n],   dx * Bv[n]);
                    h[n+1] = fmaf(pw[n+1], h[n+1], dx * Bv[n+1]);
                    y0 = fmaf(h[n],   Cv[n],   y0);
                    y1 = fmaf(h[n+1], Cv[n+1], y1);
                }
            } else {
                #pragma unroll
                for (int n = 0; n < NST; n += 2) {
                    float dA0 = __expf(delta * a[n]);
                    float dA1 = __expf(delta * a[n+1]);
                    h[n]   = fmaf(dA0, h[n],   dx * Bv[n]);
                    h[n+1] = fmaf(dA1, h[n+1], dx * Bv[n+1]);
                    y0 = fmaf(h[n],   Cv[n],   y0);
                    y1 = fmaf(h[n+1], Cv[n+1], y1);
                }
            }
            float yy = fmaf(xv, Dd, y0 + y1);
            g_ybf[(tc0 + wnd*SW + s)*DIv + ch] = __float2bfloat16(yy * zv);
        }
    }
}

// ---------------- head MLP (M=8): 320 -> 512 -> 512 -> 1 ----------------
__global__ void __launch_bounds__(512) k_head(
    const float* __restrict__ w1, const float* __restrict__ b1,
    const float* __restrict__ w2, const float* __restrict__ b2,
    const float* __restrict__ w3, const float* __restrict__ b3,
    float* __restrict__ out)
{
    __shared__ float sh [8][320];
    __shared__ float sh1[8][512];
    __shared__ float sh2[8][512];
    int tid = threadIdx.x;

    for (int idx = tid; idx < 8*320; idx += 512) {
        int bb = idx / 320, c = idx % 320;
        sh[bb][c] = g_bufA[((size_t)bb * Lq + Lq - 1) * DMv + c];
    }
    __syncthreads();

    {
        int n = tid;
        float acc[8];
        #pragma unroll
        for (int bb = 0; bb < 8; bb++) acc[bb] = 0.f;
        const float* wr = w1 + (size_t)n * 320;
        for (int k = 0; k < 320; k++) {
            float wv = wr[k];
            #pragma unroll
            for (int bb = 0; bb < 8; bb++) acc[bb] = fmaf(wv, sh[bb][k], acc[bb]);
        }
        #pragma unroll
        for (int bb = 0; bb < 8; bb++) sh1[bb][n] = fmaxf(acc[bb] + b1[n], 0.f);
    }
    __syncthreads();

    {
        int n = tid;
        float acc[8];
        #pragma unroll
        for (int bb = 0; bb < 8; bb++) acc[bb] = 0.f;
        const float* wr = w2 + (size_t)n * 512;
        for (int k = 0; k < 512; k++) {
            float wv = wr[k];
            #pragma unroll
            for (int bb = 0; bb < 8; bb++) acc[bb] = fmaf(wv, sh1[bb][k], acc[bb]);
        }
        #pragma unroll
        for (int bb = 0; bb < 8; bb++) sh2[bb][n] = fmaxf(acc[bb] + b2[n], 0.f);
    }
    __syncthreads();

    if (tid < 8) {
        float acc = 0.f;
        for (int k = 0; k < 512; k++) acc = fmaf(w3[k], sh2[tid][k], acc);
        acc += b3[0];
        float scale = g_startmax / (1.f + logf((float)Lq));
        out[tid] = fmaxf(acc * scale, 0.f);
    }
}

// ---------------- host launch ----------------
extern "C" void kernel_launch(void* const* d_in, const int* in_sizes, int n_in,
                              void* d_out, int out_size)
{
    const float* x            = (const float*)d_in[0];
    const float* fc_w         = (const float*)d_in[1];
    const float* fc_b         = (const float*)d_in[2];
    const float* blk_lin_w    = (const float*)d_in[3];
    const float* blk_lin_b    = (const float*)d_in[4];
    const float* blk_inproj_w = (const float*)d_in[5];
    const float* blk_conv_w   = (const float*)d_in[6];
    const float* blk_conv_b   = (const float*)d_in[7];
    const float* blk_xproj_w  = (const float*)d_in[8];
    const float* blk_dtproj_w = (const float*)d_in[9];
    const float* blk_dtproj_b = (const float*)d_in[10];
    const float* blk_A_log    = (const float*)d_in[11];
    const float* blk_D        = (const float*)d_in[12];
    const float* blk_outproj_w= (const float*)d_in[13];
    const float* s1_w1        = (const float*)d_in[14];
    const float* s1_b1        = (const float*)d_in[15];
    const float* s1_w2        = (const float*)d_in[16];
    const float* s1_b2        = (const float*)d_in[17];
    const float* s1_w3        = (const float*)d_in[18];
    const float* s1_b3        = (const float*)d_in[19];

    void* p;
    cudaGetSymbolAddress(&p, g_dbc);     float* dbc     = (float*)p;
    cudaGetSymbolAddress(&p, g_bufA);    float* bufA    = (float*)p;
    cudaGetSymbolAddress(&p, g_bufAbf);  bf16* bufAbf   = (bf16*)p;
    cudaGetSymbolAddress(&p, g_ubf);     bf16* ubf      = (bf16*)p;
    cudaGetSymbolAddress(&p, g_xzbf);    bf16* xzbf     = (bf16*)p;
    cudaGetSymbolAddress(&p, g_xconvbf); bf16* xconvbf  = (bf16*)p;
    cudaGetSymbolAddress(&p, g_dbcbf);   bf16* dbcbf    = (bf16*)p;
    cudaGetSymbolAddress(&p, g_deltabf); bf16* deltabf  = (bf16*)p;
    cudaGetSymbolAddress(&p, g_ybf);     bf16* ybf      = (bf16*)p;
    cudaGetSymbolAddress(&p, g_wlin);    bf16* wlin     = (bf16*)p;
    cudaGetSymbolAddress(&p, g_win);     bf16* win      = (bf16*)p;
    cudaGetSymbolAddress(&p, g_wxp);     bf16* wxp      = (bf16*)p;
    cudaGetSymbolAddress(&p, g_wdt);     bf16* wdt      = (bf16*)p;
    cudaGetSymbolAddress(&p, g_wout);    bf16* wout     = (bf16*)p;

    // merged weight conversion (1 launch)
    k_cvtall<<<(NQA + NDT + 255)/256, 256>>>(blk_lin_w, blk_inproj_w, blk_xproj_w,
                                             blk_dtproj_w, blk_outproj_w);
    k_startmax<<<1, 256>>>(x);
    k_embed<<<Tq/64, 320>>>(x, fc_w, fc_b);

    for (int i = 0; i < NBLK; i++) {
        const float* Alog = blk_A_log + (size_t)i*DIv*NST;

        // lin: tanh(bufA @ lin_w^T + b) -> u(bf16)   [Tq,320] K=320
        k_bgemm<1><<<dim3(5, Tq/128), 256>>>(
            bufAbf, DMv, wlin + (size_t)i*DMv*DMv, DMv,
            blk_lin_b + (size_t)i*DMv,
            (float*)nullptr, 0, ubf, DMv, Tq, DMv, DMv);

        // inproj: u @ inproj_w^T -> xz(bf16, silu on z half)   [Tq,2560] K=320
        k_bgemm<4><<<dim3(40, Tq/128), 256>>>(
            ubf, DMv, win + (size_t)i*2*DIv*DMv, DMv,
            (const float*)nullptr,
            (float*)nullptr, 0, xzbf, 2*DIv, Tq, 2*DIv, DMv);

        // depthwise causal conv + silu -> xconv(bf16)
        k_conv<<<dim3(Tq/16, DIv/256), 256>>>(
            blk_conv_w + (size_t)i*DIv*DCONVK, blk_conv_b + (size_t)i*DIv);

        // xproj (split-K): partials then reduce -> dbc (f32) + dbcbf (bf16)
        k_xgemm<<<dim3(KS, Tq/128), 256>>>(
            xconvbf, wxp + (size_t)i*XDv*DIv);
        k_xred<<<(Tq*XDv + 255)/256, 256>>>();

        // dtproj: softplus(dt @ dtproj_w^T + b) -> delta(bf16)   [Tq,1280] K=20
        k_bgemm<2><<<dim3(20, Tq/128), 256>>>(
            dbcbf, 56, wdt + (size_t)i*DIv*24, 24,
            blk_dtproj_b + (size_t)i*DIv,
            (float*)nullptr, 0, deltabf, DIv, Tq, DIv, DTRANK);

        // chunked selective scan -> y(bf16)
        k_scanA<<<dim3(DIv/SCH, Bq*NCH), SCH>>>(Alog);
        k_scanB<<<(Bq*NST*DIv + 255)/256, 256>>>(Alog);
        k_scanC<<<dim3(DIv/SCH, Bq*NCH), SCH>>>(Alog, blk_D + (size_t)i*DIv);

        // outproj: elu(y @ outproj_w^T) -> bufA (f32 + bf16)   [Tq,320] K=1280
        k_bgemm<3><<<dim3(5, Tq/128), 256>>>(
            ybf, DIv, wout + (size_t)i*DMv*DIv, DIv,
            (const float*)nullptr,
            bufA, DMv, bufAbf, DMv, Tq, DMv, DIv);
    }

    k_head<<<1, 512>>>(s1_w1, s1_b1, s1_w2, s1_b2, s1_w3, s1_b3, (float*)d_out);
}